// round 7
// baseline (speedup 1.0000x reference)
#include <cuda_runtime.h>
#include <cuda_bf16.h>
#include <cstdint>

#define NTOK 2048
#define NHEAD 8
#define EPSV 1e-6f
#define QKSCALE 0.17677669529663687f
#define NSPL 4
#define JR (NTOK / NSPL)      /* 512 per split */
#define TIA 32
#define TJA 32
#define NJT (JR / TJA)        /* 16 tiles */
#define RSTRB 528             /* smem row stride bytes (264 bf16) */
#define PLANEB 16896          /* 32*528 */
#define BUFB 33792            /* 2 planes */

typedef unsigned long long ull;

__device__ float g_Q[NTOK * 256];
__device__ float g_K[NTOK * 256];
__device__ float g_V[NTOK * 256];
__device__ float g_pn[NSPL * NTOK * 256];
__device__ float g_pd[NSPL * NTOK * NHEAD];
__device__ __align__(16) __nv_bfloat16 g_Qhl[2 * NTOK * 256];
__device__ __align__(16) __nv_bfloat16 g_Khl[2 * NTOK * 256];
__device__ __align__(16) __nv_bfloat16 g_Vhl[2 * NTOK * 256];

/* ---------------- f32x2 helpers ---------------- */
__device__ __forceinline__ ull ffma2(ull a, ull b, ull c) {
    ull d; asm("fma.rn.f32x2 %0, %1, %2, %3;" : "=l"(d) : "l"(a), "l"(b), "l"(c)); return d;
}
__device__ __forceinline__ ull pack2(float lo, float hi) {
    ull r; asm("mov.b64 %0, {%1, %2};" : "=l"(r) : "f"(lo), "f"(hi)); return r;
}
__device__ __forceinline__ float2 unpack2(ull v) {
    float2 r; asm("mov.b64 {%0, %1}, %2;" : "=f"(r.x), "=f"(r.y) : "l"(v)); return r;
}

/* ---------------- warp-mma / async helpers ---------------- */
__device__ __forceinline__ uint32_t smem_u32(const void* p) {
    uint32_t a;
    asm("{ .reg .u64 t; cvta.to.shared.u64 t, %1; cvt.u32.u64 %0, t; }" : "=r"(a) : "l"(p));
    return a;
}
__device__ __forceinline__ void mma16816(float* d, const uint32_t* a, const uint32_t* b) {
    asm("mma.sync.aligned.m16n8k16.row.col.f32.bf16.bf16.f32 "
        "{%0,%1,%2,%3}, {%4,%5,%6,%7}, {%8,%9}, {%0,%1,%2,%3};"
        : "+f"(d[0]), "+f"(d[1]), "+f"(d[2]), "+f"(d[3])
        : "r"(a[0]), "r"(a[1]), "r"(a[2]), "r"(a[3]), "r"(b[0]), "r"(b[1]));
}
__device__ __forceinline__ void ldsm4(uint32_t* r, uint32_t a) {
    asm volatile("ldmatrix.sync.aligned.m8n8.x4.shared.b16 {%0,%1,%2,%3}, [%4];"
                 : "=r"(r[0]), "=r"(r[1]), "=r"(r[2]), "=r"(r[3]) : "r"(a));
}
__device__ __forceinline__ void ldsm2(uint32_t* r, uint32_t a) {
    asm volatile("ldmatrix.sync.aligned.m8n8.x2.shared.b16 {%0,%1}, [%2];"
                 : "=r"(r[0]), "=r"(r[1]) : "r"(a));
}
__device__ __forceinline__ void ldsm2t(uint32_t* r, uint32_t a) {
    asm volatile("ldmatrix.sync.aligned.m8n8.x2.trans.shared.b16 {%0,%1}, [%2];"
                 : "=r"(r[0]), "=r"(r[1]) : "r"(a));
}
__device__ __forceinline__ void cpa16(uint32_t d, const void* s) {
    asm volatile("cp.async.ca.shared.global [%0], [%1], 16;" :: "r"(d), "l"(s));
}
#define CP_COMMIT() asm volatile("cp.async.commit_group;" ::: "memory")
#define CP_WAIT1()  asm volatile("cp.async.wait_group 1;" ::: "memory")
__device__ __forceinline__ void hilo(float v, __nv_bfloat16& h, __nv_bfloat16& l) {
    h = __float2bfloat16_rn(v);
    l = __float2bfloat16_rn(v - __bfloat162float(h));
}
__device__ __forceinline__ uint32_t packbf(__nv_bfloat16 a, __nv_bfloat16 b) {
    return (uint32_t)*(unsigned short*)&a | ((uint32_t)*(unsigned short*)&b << 16);
}

/* =============== projection GEMM (measured-good) =============== */
template<bool COMBINE>
__device__ __forceinline__ void gemm_body(const float* __restrict__ A,
                                          const float* __restrict__ B,
                                          float* __restrict__ C,
                                          __nv_bfloat16* __restrict__ planes)
{
    __shared__ __align__(16) float As[2][16][68];
    __shared__ __align__(16) float Bs[2][16][68];
    const int t = threadIdx.x, tx = t & 15, ty = t >> 4;
    const int bi = blockIdx.y, bj = blockIdx.x;
    const int row = t >> 2, k4 = (t & 3) * 4;
    const int arow = bi * 64 + row;
    const float* Bg = B + (size_t)(bj * 64 + row) * 256 + k4;

    auto loadA = [&](int c0) -> float4 {
        if (COMBINE) {
            float4 n = *(const float4*)(g_pn + (size_t)arow * 256 + c0);
            float den = g_pd[arow * NHEAD + (c0 >> 5)];
#pragma unroll
            for (int s = 1; s < NSPL; s++) {
                float4 n2 = *(const float4*)(g_pn + (size_t)s * NTOK * 256 + (size_t)arow * 256 + c0);
                n.x += n2.x; n.y += n2.y; n.z += n2.z; n.w += n2.w;
                den += g_pd[s * NTOK * NHEAD + arow * NHEAD + (c0 >> 5)];
            }
            float inv = 1.0f / den;
            return make_float4(n.x * inv, n.y * inv, n.z * inv, n.w * inv);
        }
        return *(const float4*)(A + (size_t)arow * 256 + c0);
    };

    float4 av = loadA(k4), bv = *(const float4*)Bg;
    As[0][k4 + 0][row] = av.x; As[0][k4 + 1][row] = av.y; As[0][k4 + 2][row] = av.z; As[0][k4 + 3][row] = av.w;
    Bs[0][k4 + 0][row] = bv.x; Bs[0][k4 + 1][row] = bv.y; Bs[0][k4 + 2][row] = bv.z; Bs[0][k4 + 3][row] = bv.w;
    __syncthreads();
    ull acc2[4][2];
#pragma unroll
    for (int r = 0; r < 4; r++) { acc2[r][0] = 0ull; acc2[r][1] = 0ull; }
    for (int kt = 0; kt < 16; kt++) {
        const int cur = kt & 1;
        if (kt < 15) { av = loadA((kt + 1) * 16 + k4); bv = *(const float4*)(Bg + (kt + 1) * 16); }
#pragma unroll
        for (int kk = 0; kk < 16; kk++) {
            float4 a = *(const float4*)&As[cur][kk][ty * 4];
            ull b0 = *(const ull*)&Bs[cur][kk][tx * 4];
            ull b1 = *(const ull*)&Bs[cur][kk][tx * 4 + 2];
            ull a0 = pack2(a.x, a.x); acc2[0][0] = ffma2(a0, b0, acc2[0][0]); acc2[0][1] = ffma2(a0, b1, acc2[0][1]);
            ull a1 = pack2(a.y, a.y); acc2[1][0] = ffma2(a1, b0, acc2[1][0]); acc2[1][1] = ffma2(a1, b1, acc2[1][1]);
            ull a2 = pack2(a.z, a.z); acc2[2][0] = ffma2(a2, b0, acc2[2][0]); acc2[2][1] = ffma2(a2, b1, acc2[2][1]);
            ull a3 = pack2(a.w, a.w); acc2[3][0] = ffma2(a3, b0, acc2[3][0]); acc2[3][1] = ffma2(a3, b1, acc2[3][1]);
        }
        if (kt < 15) {
            const int nx = cur ^ 1;
            As[nx][k4 + 0][row] = av.x; As[nx][k4 + 1][row] = av.y; As[nx][k4 + 2][row] = av.z; As[nx][k4 + 3][row] = av.w;
            Bs[nx][k4 + 0][row] = bv.x; Bs[nx][k4 + 1][row] = bv.y; Bs[nx][k4 + 2][row] = bv.z; Bs[nx][k4 + 3][row] = bv.w;
        }
        __syncthreads();
    }
#pragma unroll
    for (int r = 0; r < 4; r++) {
        float2 lo = unpack2(acc2[r][0]), hi = unpack2(acc2[r][1]);
        float4 o = make_float4(lo.x, lo.y, hi.x, hi.y);
        const size_t orow = (size_t)(bi * 64 + ty * 4 + r);
        const int ocol = bj * 64 + tx * 4;
        *(float4*)(C + orow * 256 + ocol) = o;
        if (planes) {
            __nv_bfloat16 h0, l0, h1, l1, h2, l2, h3, l3;
            hilo(o.x, h0, l0); hilo(o.y, h1, l1); hilo(o.z, h2, l2); hilo(o.w, h3, l3);
            ull hp = (ull)packbf(h0, h1) | ((ull)packbf(h2, h3) << 32);
            ull lp = (ull)packbf(l0, l1) | ((ull)packbf(l2, l3) << 32);
            *(ull*)(planes + orow * 256 + ocol) = hp;
            *(ull*)(planes + (size_t)NTOK * 256 + orow * 256 + ocol) = lp;
        }
    }
}

__global__ __launch_bounds__(256) void gemm_qkv(const float* __restrict__ x,
                                                const float* __restrict__ Wq,
                                                const float* __restrict__ Wk,
                                                const float* __restrict__ Wv)
{
    const float* B = (blockIdx.z == 0) ? Wq : (blockIdx.z == 1) ? Wk : Wv;
    float*       C = (blockIdx.z == 0) ? g_Q : (blockIdx.z == 1) ? g_K : g_V;
    __nv_bfloat16* P = (blockIdx.z == 0) ? g_Qhl : (blockIdx.z == 1) ? g_Khl : g_Vhl;
    gemm_body<false>(x, B, C, P);
}
__global__ __launch_bounds__(256) void gemm_out(const float* __restrict__ Wo, float* __restrict__ out)
{
    gemm_body<true>(nullptr, Wo, out, nullptr);
}

/* =============== warp-mma attention, cp.async double-buffered =============== */
#define OFF_K   0                     /* [2 buf][2 plane][32][528B] */
#define OFF_V   (2 * BUFB)            /* 67584 */
#define OFF_W   (4 * BUFB)            /* 135168: float Ws[8][32][33] */
#define OFF_PIT (OFF_W + 33792)       /* 168960: float pits[32][32] */
#define SMEM_BYTES (OFF_PIT + 4096)   /* 173056 */

__global__ __launch_bounds__(256) void attn_mma(
    const float* __restrict__ pi, const float* __restrict__ tau,
    const float* __restrict__ adjs)
{
    extern __shared__ __align__(16) char smraw[];
    const uint32_t sb = smem_u32(smraw);
    float* Ws   = (float*)(smraw + OFF_W);
    float* pits = (float*)(smraw + OFF_PIT);

    const int t = threadIdx.x, lane = t & 31, h = t >> 5;
    const int i0 = blockIdx.x * TIA;
    const int sy = blockIdx.y;
    const int jbase = sy * JR;
    const size_t NN = (size_t)NTOK * NTOK;

    for (int idx = t; idx < TIA * 32; idx += 256) {
        int hm = idx & 31;
        pits[idx] = tau[hm >> 2] * pi[(size_t)(i0 + (idx >> 5)) * 32 + hm];
    }

    /* ---- stage Q hi/lo planes into K buf0, pull A-fragments ---- */
#pragma unroll
    for (int k = 0; k < 8; k++) {
        int idx = t + k * 256;          /* 2048 chunks of 16B */
        int plane = idx >> 10, r3 = idx & 1023, row = r3 >> 5, c16 = r3 & 31;
        ull v = *(const ull*)(g_Qhl + (size_t)plane * NTOK * 256 + (size_t)(i0 + row) * 256 + c16 * 8);
        ull v2 = *(const ull*)(g_Qhl + (size_t)plane * NTOK * 256 + (size_t)(i0 + row) * 256 + c16 * 8 + 4);
        char* d = smraw + OFF_K + plane * PLANEB + row * RSTRB + c16 * 16;
        *(ull*)d = v; *(ull*)(d + 8) = v2;
    }
    __syncthreads();
    uint32_t qh[2][2][4], ql[2][2][4];
#pragma unroll
    for (int it = 0; it < 2; it++)
#pragma unroll
        for (int ks = 0; ks < 2; ks++) {
            int row = it * 16 + (lane & 15);
            int col = 32 * h + ks * 16 + (lane >> 4) * 8;
            uint32_t a0 = sb + OFF_K + row * RSTRB + col * 2;
            ldsm4(qh[it][ks], a0);
            ldsm4(ql[it][ks], a0 + PLANEB);
        }
    __syncthreads();

    /* per-thread cp.async mapping (16 chunks: K/V x plane x row x col16) */
    uint32_t cdst[16];
    const __nv_bfloat16* csrc_base[16];
    int crow[16];
#pragma unroll
    for (int k = 0; k < 16; k++) {
        int idx = t + k * 256;
        int arr = idx >> 11, r2 = idx & 2047;
        int plane = r2 >> 10, r3 = r2 & 1023, row = r3 >> 5, c16 = r3 & 31;
        cdst[k] = sb + (arr ? OFF_V : OFF_K) + plane * PLANEB + row * RSTRB + c16 * 16;
        csrc_base[k] = (arr ? g_Vhl : g_Khl) + (size_t)plane * NTOK * 256 + c16 * 8;
        crow[k] = row;
    }

    /* prefetch tile 0 into buf 0 */
    {
        const int j0 = jbase;
#pragma unroll
        for (int k = 0; k < 16; k++)
            cpa16(cdst[k], csrc_base[k] + (size_t)(j0 + crow[k]) * 256);
        CP_COMMIT();
    }

    float O[2][4][4];
#pragma unroll
    for (int it = 0; it < 2; it++)
#pragma unroll
        for (int n8 = 0; n8 < 4; n8++)
#pragma unroll
            for (int c = 0; c < 4; c++) O[it][n8][c] = 0.f;
    float rsum[4] = {0.f, 0.f, 0.f, 0.f};

    const int wi = t >> 3;          /* Ws identity */
    const int wj4 = (t & 7) * 4;

    for (int jt = 0; jt < NJT; jt++) {
        const int cur = jt & 1;
        const int j0 = jbase + jt * TJA;
        __syncthreads();   /* Ws reads of prev tile done; prev MMA buf reads done */

        /* adjs loads for this tile (start early) */
        const float* ab = adjs + (size_t)(i0 + wi) * NTOK + j0 + wj4;
        float4 a0 = *(const float4*)(ab);
        float4 a1 = *(const float4*)(ab + NN);
        float4 a2 = *(const float4*)(ab + 2 * NN);
        float4 a3 = *(const float4*)(ab + 3 * NN);

        /* prefetch next tile into other buffer */
        if (jt + 1 < NJT) {
            const int jn = j0 + TJA;
            const uint32_t boff = (cur ^ 1) * BUFB;
#pragma unroll
            for (int k = 0; k < 16; k++)
                cpa16(cdst[k] + boff, csrc_base[k] + (size_t)(jn + crow[k]) * 256);
        }
        CP_COMMIT();

        /* graph weights Ws[h][i][j] */
        {
            const float* pp = pits + wi * 32;
#pragma unroll
            for (int hh = 0; hh < NHEAD; hh++) {
                float p0 = pp[hh * 4 + 0], p1 = pp[hh * 4 + 1], p2 = pp[hh * 4 + 2], p3 = pp[hh * 4 + 3];
                float* wd = Ws + (hh * 32 + wi) * 33 + wj4;
                wd[0] = fmaf(p3, a3.x, fmaf(p2, a2.x, fmaf(p1, a1.x, fmaf(p0, a0.x, EPSV))));
                wd[1] = fmaf(p3, a3.y, fmaf(p2, a2.y, fmaf(p1, a1.y, fmaf(p0, a0.y, EPSV))));
                wd[2] = fmaf(p3, a3.z, fmaf(p2, a2.z, fmaf(p1, a1.z, fmaf(p0, a0.z, EPSV))));
                wd[3] = fmaf(p3, a3.w, fmaf(p2, a2.w, fmaf(p1, a1.w, fmaf(p0, a0.w, EPSV))));
            }
        }
        CP_WAIT1();        /* this tile's K/V landed (next tile still in flight) */
        __syncthreads();

        /* ---- QK^T, error-compensated ---- */
        float S[2][4][4];
#pragma unroll
        for (int it = 0; it < 2; it++)
#pragma unroll
            for (int j8 = 0; j8 < 4; j8++)
#pragma unroll
                for (int c = 0; c < 4; c++) S[it][j8][c] = 0.f;
        const uint32_t kbase = sb + OFF_K + cur * BUFB;
#pragma unroll
        for (int j8 = 0; j8 < 4; j8++)
#pragma unroll
            for (int ks = 0; ks < 2; ks++) {
                int krow = j8 * 8 + (lane & 7);
                int kcol = 32 * h + ks * 16 + ((lane >> 3) & 1) * 8;
                uint32_t ad = kbase + krow * RSTRB + kcol * 2;
                uint32_t bh[2], bl[2];
                ldsm2(bh, ad);
                ldsm2(bl, ad + PLANEB);
#pragma unroll
                for (int it = 0; it < 2; it++) {
                    mma16816(S[it][j8], qh[it][ks], bh);
                    mma16816(S[it][j8], qh[it][ks], bl);
                    mma16816(S[it][j8], ql[it][ks], bh);
                }
            }

        /* ---- p = w * exp(s*scale); repack to A-frag hi/lo ---- */
        uint32_t ph[2][2][4], pl[2][2][4];
#pragma unroll
        for (int it = 0; it < 2; it++)
#pragma unroll
            for (int j8 = 0; j8 < 4; j8++) {
                int r0 = it * 16 + (lane >> 2);
                int c0 = j8 * 8 + 2 * (lane & 3);
                const float* wr0 = Ws + (h * 32 + r0) * 33 + c0;
                const float* wr1 = Ws + (h * 32 + r0 + 8) * 33 + c0;
                float p0 = wr0[0] * __expf(S[it][j8][0] * QKSCALE);
                float p1 = wr0[1] * __expf(S[it][j8][1] * QKSCALE);
                float p2 = wr1[0] * __expf(S[it][j8][2] * QKSCALE);
                float p3 = wr1[1] * __expf(S[it][j8][3] * QKSCALE);
                rsum[it * 2 + 0] += p0 + p1;
                rsum[it * 2 + 1] += p2 + p3;
                __nv_bfloat16 h0, l0, h1, l1, h2, l2, h3, l3;
                hilo(p0, h0, l0); hilo(p1, h1, l1); hilo(p2, h2, l2); hilo(p3, h3, l3);
                int kc = j8 >> 1, sl = (j8 & 1) * 2;
                ph[it][kc][sl + 0] = packbf(h0, h1);
                ph[it][kc][sl + 1] = packbf(h2, h3);
                pl[it][kc][sl + 0] = packbf(l0, l1);
                pl[it][kc][sl + 1] = packbf(l2, l3);
            }

        /* ---- O += P @ V, error-compensated ---- */
        const uint32_t vbase = sb + OFF_V + cur * BUFB;
#pragma unroll
        for (int n8 = 0; n8 < 4; n8++)
#pragma unroll
            for (int kc = 0; kc < 2; kc++) {
                int vrow = kc * 16 + (lane & 15);
                int vcol = 32 * h + n8 * 8;
                uint32_t ad = vbase + vrow * RSTRB + vcol * 2;
                uint32_t vh[2], vl[2];
                ldsm2t(vh, ad);
                ldsm2t(vl, ad + PLANEB);
#pragma unroll
                for (int it = 0; it < 2; it++) {
                    mma16816(O[it][n8], ph[it][kc], vh);
                    mma16816(O[it][n8], ph[it][kc], vl);
                    mma16816(O[it][n8], pl[it][kc], vh);
                }
            }
    }

    /* ---- epilogue ---- */
#pragma unroll
    for (int v = 0; v < 4; v++) {
        float x = rsum[v];
        x += __shfl_xor_sync(0xffffffffu, x, 1);
        x += __shfl_xor_sync(0xffffffffu, x, 2);
        rsum[v] = x;
    }
    if ((lane & 3) == 0) {
#pragma unroll
        for (int it = 0; it < 2; it++)
#pragma unroll
            for (int half = 0; half < 2; half++) {
                int row = it * 16 + (lane >> 2) + half * 8;
                g_pd[(size_t)sy * NTOK * NHEAD + (size_t)(i0 + row) * NHEAD + h] = rsum[it * 2 + half];
            }
    }
    float* pn = g_pn + (size_t)sy * NTOK * 256;
#pragma unroll
    for (int it = 0; it < 2; it++)
#pragma unroll
        for (int n8 = 0; n8 < 4; n8++) {
            int r0 = i0 + it * 16 + (lane >> 2);
            int c = 32 * h + n8 * 8 + 2 * (lane & 3);
            *(float2*)(pn + (size_t)r0 * 256 + c) = make_float2(O[it][n8][0], O[it][n8][1]);
            *(float2*)(pn + (size_t)(r0 + 8) * 256 + c) = make_float2(O[it][n8][2], O[it][n8][3]);
        }
}

/* ================================================================= */
extern "C" void kernel_launch(void* const* d_in, const int* in_sizes, int n_in,
                              void* d_out, int out_size)
{
    const float* x    = (const float*)d_in[0];
    const float* pi   = (const float*)d_in[1];
    const float* tau  = (const float*)d_in[2];
    const float* adjs = (const float*)d_in[3];
    const float* Wq   = (const float*)d_in[4];
    const float* Wk   = (const float*)d_in[5];
    const float* Wv   = (const float*)d_in[6];
    const float* Wo   = (const float*)d_in[7];
    float* out = (float*)d_out;

    cudaFuncSetAttribute(attn_mma, cudaFuncAttributeMaxDynamicSharedMemorySize, SMEM_BYTES);

    gemm_qkv<<<dim3(4, 32, 3), 256>>>(x, Wq, Wk, Wv);
    attn_mma<<<dim3(NTOK / TIA, NSPL), 256, SMEM_BYTES>>>(pi, tau, adjs);
    gemm_out<<<dim3(4, 32), 256>>>(Wo, out);
}

// round 8
// speedup vs baseline: 1.1347x; 1.1347x over previous
#include <cuda_runtime.h>
#include <cuda_fp16.h>
#include <cstdint>

#define NTOK 2048
#define NHEAD 8
#define EPSV 1e-6f
#define QKSCALE 0.17677669529663687f
#define PSCALE 1024.0f
#define INV_PSCALE (1.0f / 1024.0f)
#define NSPL 4
#define JR (NTOK / NSPL)      /* 512 per split */
#define TIA 32
#define TJA 32
#define NJT (JR / TJA)        /* 16 tiles */
#define RSTRB 528             /* smem row stride bytes (264 fp16) */
#define PLANEB 16896          /* 32*528 */
#define BUFB 33792            /* 2 planes */

typedef unsigned long long ull;

__device__ float g_Q[NTOK * 256];
__device__ float g_K[NTOK * 256];
__device__ float g_V[NTOK * 256];
__device__ float g_pn[NSPL * NTOK * 256];
__device__ float g_pd[NSPL * NTOK * NHEAD];
__device__ __align__(16) __half g_Qhl[2 * NTOK * 256];
__device__ __align__(16) __half g_Khl[2 * NTOK * 256];
__device__ __align__(16) __half g_Vhl[2 * NTOK * 256];

/* ---------------- f32x2 helpers ---------------- */
__device__ __forceinline__ ull ffma2(ull a, ull b, ull c) {
    ull d; asm("fma.rn.f32x2 %0, %1, %2, %3;" : "=l"(d) : "l"(a), "l"(b), "l"(c)); return d;
}
__device__ __forceinline__ ull pack2(float lo, float hi) {
    ull r; asm("mov.b64 %0, {%1, %2};" : "=l"(r) : "f"(lo), "f"(hi)); return r;
}
__device__ __forceinline__ float2 unpack2(ull v) {
    float2 r; asm("mov.b64 {%0, %1}, %2;" : "=f"(r.x), "=f"(r.y) : "l"(v)); return r;
}

/* ---------------- warp-mma / async helpers ---------------- */
__device__ __forceinline__ uint32_t smem_u32(const void* p) {
    uint32_t a;
    asm("{ .reg .u64 t; cvta.to.shared.u64 t, %1; cvt.u32.u64 %0, t; }" : "=r"(a) : "l"(p));
    return a;
}
__device__ __forceinline__ void mma16816(float* d, const uint32_t* a, const uint32_t* b) {
    asm("mma.sync.aligned.m16n8k16.row.col.f32.f16.f16.f32 "
        "{%0,%1,%2,%3}, {%4,%5,%6,%7}, {%8,%9}, {%0,%1,%2,%3};"
        : "+f"(d[0]), "+f"(d[1]), "+f"(d[2]), "+f"(d[3])
        : "r"(a[0]), "r"(a[1]), "r"(a[2]), "r"(a[3]), "r"(b[0]), "r"(b[1]));
}
__device__ __forceinline__ void ldsm4(uint32_t* r, uint32_t a) {
    asm volatile("ldmatrix.sync.aligned.m8n8.x4.shared.b16 {%0,%1,%2,%3}, [%4];"
                 : "=r"(r[0]), "=r"(r[1]), "=r"(r[2]), "=r"(r[3]) : "r"(a));
}
__device__ __forceinline__ void ldsm2(uint32_t* r, uint32_t a) {
    asm volatile("ldmatrix.sync.aligned.m8n8.x2.shared.b16 {%0,%1}, [%2];"
                 : "=r"(r[0]), "=r"(r[1]) : "r"(a));
}
__device__ __forceinline__ void ldsm2t(uint32_t* r, uint32_t a) {
    asm volatile("ldmatrix.sync.aligned.m8n8.x2.trans.shared.b16 {%0,%1}, [%2];"
                 : "=r"(r[0]), "=r"(r[1]) : "r"(a));
}
__device__ __forceinline__ void cpa16(uint32_t d, const void* s) {
    asm volatile("cp.async.ca.shared.global [%0], [%1], 16;" :: "r"(d), "l"(s));
}
#define CP_COMMIT() asm volatile("cp.async.commit_group;" ::: "memory")
#define CP_WAIT1()  asm volatile("cp.async.wait_group 1;" ::: "memory")
__device__ __forceinline__ void hiloh(float v, __half& h, __half& l) {
    h = __float2half_rn(v);
    l = __float2half_rn(v - __half2float(h));
}
__device__ __forceinline__ uint32_t packh(__half a, __half b) {
    return (uint32_t)*(unsigned short*)&a | ((uint32_t)*(unsigned short*)&b << 16);
}

/* =============== projection GEMM (measured-good) =============== */
template<bool COMBINE>
__device__ __forceinline__ void gemm_body(const float* __restrict__ A,
                                          const float* __restrict__ B,
                                          float* __restrict__ C,
                                          __half* __restrict__ planes)
{
    __shared__ __align__(16) float As[2][16][68];
    __shared__ __align__(16) float Bs[2][16][68];
    const int t = threadIdx.x, tx = t & 15, ty = t >> 4;
    const int bi = blockIdx.y, bj = blockIdx.x;
    const int row = t >> 2, k4 = (t & 3) * 4;
    const int arow = bi * 64 + row;
    const float* Bg = B + (size_t)(bj * 64 + row) * 256 + k4;

    auto loadA = [&](int c0) -> float4 {
        if (COMBINE) {
            float4 n = *(const float4*)(g_pn + (size_t)arow * 256 + c0);
            float den = g_pd[arow * NHEAD + (c0 >> 5)];
#pragma unroll
            for (int s = 1; s < NSPL; s++) {
                float4 n2 = *(const float4*)(g_pn + (size_t)s * NTOK * 256 + (size_t)arow * 256 + c0);
                n.x += n2.x; n.y += n2.y; n.z += n2.z; n.w += n2.w;
                den += g_pd[s * NTOK * NHEAD + arow * NHEAD + (c0 >> 5)];
            }
            float inv = 1.0f / den;
            return make_float4(n.x * inv, n.y * inv, n.z * inv, n.w * inv);
        }
        return *(const float4*)(A + (size_t)arow * 256 + c0);
    };

    float4 av = loadA(k4), bv = *(const float4*)Bg;
    As[0][k4 + 0][row] = av.x; As[0][k4 + 1][row] = av.y; As[0][k4 + 2][row] = av.z; As[0][k4 + 3][row] = av.w;
    Bs[0][k4 + 0][row] = bv.x; Bs[0][k4 + 1][row] = bv.y; Bs[0][k4 + 2][row] = bv.z; Bs[0][k4 + 3][row] = bv.w;
    __syncthreads();
    ull acc2[4][2];
#pragma unroll
    for (int r = 0; r < 4; r++) { acc2[r][0] = 0ull; acc2[r][1] = 0ull; }
    for (int kt = 0; kt < 16; kt++) {
        const int cur = kt & 1;
        if (kt < 15) { av = loadA((kt + 1) * 16 + k4); bv = *(const float4*)(Bg + (kt + 1) * 16); }
#pragma unroll
        for (int kk = 0; kk < 16; kk++) {
            float4 a = *(const float4*)&As[cur][kk][ty * 4];
            ull b0 = *(const ull*)&Bs[cur][kk][tx * 4];
            ull b1 = *(const ull*)&Bs[cur][kk][tx * 4 + 2];
            ull a0 = pack2(a.x, a.x); acc2[0][0] = ffma2(a0, b0, acc2[0][0]); acc2[0][1] = ffma2(a0, b1, acc2[0][1]);
            ull a1 = pack2(a.y, a.y); acc2[1][0] = ffma2(a1, b0, acc2[1][0]); acc2[1][1] = ffma2(a1, b1, acc2[1][1]);
            ull a2 = pack2(a.z, a.z); acc2[2][0] = ffma2(a2, b0, acc2[2][0]); acc2[2][1] = ffma2(a2, b1, acc2[2][1]);
            ull a3 = pack2(a.w, a.w); acc2[3][0] = ffma2(a3, b0, acc2[3][0]); acc2[3][1] = ffma2(a3, b1, acc2[3][1]);
        }
        if (kt < 15) {
            const int nx = cur ^ 1;
            As[nx][k4 + 0][row] = av.x; As[nx][k4 + 1][row] = av.y; As[nx][k4 + 2][row] = av.z; As[nx][k4 + 3][row] = av.w;
            Bs[nx][k4 + 0][row] = bv.x; Bs[nx][k4 + 1][row] = bv.y; Bs[nx][k4 + 2][row] = bv.z; Bs[nx][k4 + 3][row] = bv.w;
        }
        __syncthreads();
    }
#pragma unroll
    for (int r = 0; r < 4; r++) {
        float2 lo = unpack2(acc2[r][0]), hi = unpack2(acc2[r][1]);
        float4 o = make_float4(lo.x, lo.y, hi.x, hi.y);
        const size_t orow = (size_t)(bi * 64 + ty * 4 + r);
        const int ocol = bj * 64 + tx * 4;
        *(float4*)(C + orow * 256 + ocol) = o;
        if (planes) {
            __half h0, l0, h1, l1, h2, l2, h3, l3;
            hiloh(o.x, h0, l0); hiloh(o.y, h1, l1); hiloh(o.z, h2, l2); hiloh(o.w, h3, l3);
            ull hp = (ull)packh(h0, h1) | ((ull)packh(h2, h3) << 32);
            ull lp = (ull)packh(l0, l1) | ((ull)packh(l2, l3) << 32);
            *(ull*)(planes + orow * 256 + ocol) = hp;
            *(ull*)(planes + (size_t)NTOK * 256 + orow * 256 + ocol) = lp;
        }
    }
}

__global__ __launch_bounds__(256) void gemm_qkv(const float* __restrict__ x,
                                                const float* __restrict__ Wq,
                                                const float* __restrict__ Wk,
                                                const float* __restrict__ Wv)
{
    const float* B = (blockIdx.z == 0) ? Wq : (blockIdx.z == 1) ? Wk : Wv;
    float*       C = (blockIdx.z == 0) ? g_Q : (blockIdx.z == 1) ? g_K : g_V;
    __half*      P = (blockIdx.z == 0) ? g_Qhl : (blockIdx.z == 1) ? g_Khl : g_Vhl;
    gemm_body<false>(x, B, C, P);
}
__global__ __launch_bounds__(256) void gemm_out(const float* __restrict__ Wo, float* __restrict__ out)
{
    gemm_body<true>(nullptr, Wo, out, nullptr);
}

/* =============== warp-mma attention, fp16 2-term compensation =============== */
#define OFF_K   0                     /* [2 buf][2 plane][32][528B] */
#define OFF_V   (2 * BUFB)            /* 67584 */
#define OFF_W   (4 * BUFB)            /* 135168: float Ws[8][32][33] */
#define OFF_PIT (OFF_W + 33792)       /* 168960: float pits[32][32] */
#define SMEM_BYTES (OFF_PIT + 4096)   /* 173056 */

__global__ __launch_bounds__(256) void attn_mma(
    const float* __restrict__ pi, const float* __restrict__ tau,
    const float* __restrict__ adjs)
{
    extern __shared__ __align__(16) char smraw[];
    const uint32_t sb = smem_u32(smraw);
    float* Ws   = (float*)(smraw + OFF_W);
    float* pits = (float*)(smraw + OFF_PIT);

    const int t = threadIdx.x, lane = t & 31, h = t >> 5;
    const int i0 = blockIdx.x * TIA;
    const int sy = blockIdx.y;
    const int jbase = sy * JR;
    const size_t NN = (size_t)NTOK * NTOK;

    for (int idx = t; idx < TIA * 32; idx += 256) {
        int hm = idx & 31;
        pits[idx] = tau[hm >> 2] * pi[(size_t)(i0 + (idx >> 5)) * 32 + hm];
    }

    /* ---- stage Q hi/lo planes into K buf0, pull A-fragments ---- */
#pragma unroll
    for (int k = 0; k < 8; k++) {
        int idx = t + k * 256;          /* 2048 chunks of 16B */
        int plane = idx >> 10, r3 = idx & 1023, row = r3 >> 5, c16 = r3 & 31;
        ull v = *(const ull*)(g_Qhl + (size_t)plane * NTOK * 256 + (size_t)(i0 + row) * 256 + c16 * 8);
        ull v2 = *(const ull*)(g_Qhl + (size_t)plane * NTOK * 256 + (size_t)(i0 + row) * 256 + c16 * 8 + 4);
        char* d = smraw + OFF_K + plane * PLANEB + row * RSTRB + c16 * 16;
        *(ull*)d = v; *(ull*)(d + 8) = v2;
    }
    __syncthreads();
    uint32_t qh[2][2][4], ql[2][2][4];
#pragma unroll
    for (int it = 0; it < 2; it++)
#pragma unroll
        for (int ks = 0; ks < 2; ks++) {
            int row = it * 16 + (lane & 15);
            int col = 32 * h + ks * 16 + (lane >> 4) * 8;
            uint32_t a0 = sb + OFF_K + row * RSTRB + col * 2;
            ldsm4(qh[it][ks], a0);
            ldsm4(ql[it][ks], a0 + PLANEB);
        }
    __syncthreads();

    /* per-thread cp.async mapping (16 chunks: K/V x plane x row x col16) */
    uint32_t cdst[16];
    const __half* csrc_base[16];
    int crow[16];
#pragma unroll
    for (int k = 0; k < 16; k++) {
        int idx = t + k * 256;
        int arr = idx >> 11, r2 = idx & 2047;
        int plane = r2 >> 10, r3 = r2 & 1023, row = r3 >> 5, c16 = r3 & 31;
        cdst[k] = sb + (arr ? OFF_V : OFF_K) + plane * PLANEB + row * RSTRB + c16 * 16;
        csrc_base[k] = (arr ? g_Vhl : g_Khl) + (size_t)plane * NTOK * 256 + c16 * 8;
        crow[k] = row;
    }

    /* prefetch tile 0 into buf 0 */
    {
        const int j0 = jbase;
#pragma unroll
        for (int k = 0; k < 16; k++)
            cpa16(cdst[k], csrc_base[k] + (size_t)(j0 + crow[k]) * 256);
        CP_COMMIT();
    }

    float O[2][4][4];
#pragma unroll
    for (int it = 0; it < 2; it++)
#pragma unroll
        for (int n8 = 0; n8 < 4; n8++)
#pragma unroll
            for (int c = 0; c < 4; c++) O[it][n8][c] = 0.f;
    float rsum[4] = {0.f, 0.f, 0.f, 0.f};

    const int wi = t >> 3;          /* Ws identity */
    const int wj4 = (t & 7) * 4;

    for (int jt = 0; jt < NJT; jt++) {
        const int cur = jt & 1;
        const int j0 = jbase + jt * TJA;
        __syncthreads();

        /* adjs loads for this tile (start early) */
        const float* ab = adjs + (size_t)(i0 + wi) * NTOK + j0 + wj4;
        float4 a0 = *(const float4*)(ab);
        float4 a1 = *(const float4*)(ab + NN);
        float4 a2 = *(const float4*)(ab + 2 * NN);
        float4 a3 = *(const float4*)(ab + 3 * NN);

        /* prefetch next tile into other buffer */
        if (jt + 1 < NJT) {
            const int jn = j0 + TJA;
            const uint32_t boff = (cur ^ 1) * BUFB;
#pragma unroll
            for (int k = 0; k < 16; k++)
                cpa16(cdst[k] + boff, csrc_base[k] + (size_t)(jn + crow[k]) * 256);
        }
        CP_COMMIT();

        /* graph weights Ws[h][i][j] */
        {
            const float* pp = pits + wi * 32;
#pragma unroll
            for (int hh = 0; hh < NHEAD; hh++) {
                float p0 = pp[hh * 4 + 0], p1 = pp[hh * 4 + 1], p2 = pp[hh * 4 + 2], p3 = pp[hh * 4 + 3];
                float* wd = Ws + (hh * 32 + wi) * 33 + wj4;
                wd[0] = fmaf(p3, a3.x, fmaf(p2, a2.x, fmaf(p1, a1.x, fmaf(p0, a0.x, EPSV))));
                wd[1] = fmaf(p3, a3.y, fmaf(p2, a2.y, fmaf(p1, a1.y, fmaf(p0, a0.y, EPSV))));
                wd[2] = fmaf(p3, a3.z, fmaf(p2, a2.z, fmaf(p1, a1.z, fmaf(p0, a0.z, EPSV))));
                wd[3] = fmaf(p3, a3.w, fmaf(p2, a2.w, fmaf(p1, a1.w, fmaf(p0, a0.w, EPSV))));
            }
        }
        CP_WAIT1();
        __syncthreads();

        /* ---- QK^T: S = Qh*Kh + Ql*Kh (fp16 2-term) ---- */
        float S[2][4][4];
#pragma unroll
        for (int it = 0; it < 2; it++)
#pragma unroll
            for (int j8 = 0; j8 < 4; j8++)
#pragma unroll
                for (int c = 0; c < 4; c++) S[it][j8][c] = 0.f;
        const uint32_t kbase = sb + OFF_K + cur * BUFB;
#pragma unroll
        for (int j8 = 0; j8 < 4; j8++)
#pragma unroll
            for (int ks = 0; ks < 2; ks++) {
                int krow = j8 * 8 + (lane & 7);
                int kcol = 32 * h + ks * 16 + ((lane >> 3) & 1) * 8;
                uint32_t ad = kbase + krow * RSTRB + kcol * 2;
                uint32_t bh[2];
                ldsm2(bh, ad);
#pragma unroll
                for (int it = 0; it < 2; it++) {
                    mma16816(S[it][j8], qh[it][ks], bh);
                    mma16816(S[it][j8], ql[it][ks], bh);
                }
            }

        /* ---- p = w * exp(s*scale); single fp16 P (scaled) ---- */
        uint32_t ph[2][2][4];
#pragma unroll
        for (int it = 0; it < 2; it++)
#pragma unroll
            for (int j8 = 0; j8 < 4; j8++) {
                int r0 = it * 16 + (lane >> 2);
                int c0 = j8 * 8 + 2 * (lane & 3);
                const float* wr0 = Ws + (h * 32 + r0) * 33 + c0;
                const float* wr1 = Ws + (h * 32 + r0 + 8) * 33 + c0;
                float p0 = wr0[0] * __expf(S[it][j8][0] * QKSCALE);
                float p1 = wr0[1] * __expf(S[it][j8][1] * QKSCALE);
                float p2 = wr1[0] * __expf(S[it][j8][2] * QKSCALE);
                float p3 = wr1[1] * __expf(S[it][j8][3] * QKSCALE);
                rsum[it * 2 + 0] += p0 + p1;
                rsum[it * 2 + 1] += p2 + p3;
                __half f0 = __float2half_rn(p0 * PSCALE);
                __half f1 = __float2half_rn(p1 * PSCALE);
                __half f2 = __float2half_rn(p2 * PSCALE);
                __half f3 = __float2half_rn(p3 * PSCALE);
                int kc = j8 >> 1, sl = (j8 & 1) * 2;
                ph[it][kc][sl + 0] = packh(f0, f1);
                ph[it][kc][sl + 1] = packh(f2, f3);
            }

        /* ---- O += P @ (Vh + Vl) (fp16 2-term) ---- */
        const uint32_t vbase = sb + OFF_V + cur * BUFB;
#pragma unroll
        for (int n8 = 0; n8 < 4; n8++)
#pragma unroll
            for (int kc = 0; kc < 2; kc++) {
                int vrow = kc * 16 + (lane & 15);
                int vcol = 32 * h + n8 * 8;
                uint32_t ad = vbase + vrow * RSTRB + vcol * 2;
                uint32_t vh[2], vl[2];
                ldsm2t(vh, ad);
                ldsm2t(vl, ad + PLANEB);
#pragma unroll
                for (int it = 0; it < 2; it++) {
                    mma16816(O[it][n8], ph[it][kc], vh);
                    mma16816(O[it][n8], ph[it][kc], vl);
                }
            }
    }

    /* ---- epilogue ---- */
#pragma unroll
    for (int v = 0; v < 4; v++) {
        float x = rsum[v];
        x += __shfl_xor_sync(0xffffffffu, x, 1);
        x += __shfl_xor_sync(0xffffffffu, x, 2);
        rsum[v] = x;
    }
    if ((lane & 3) == 0) {
#pragma unroll
        for (int it = 0; it < 2; it++)
#pragma unroll
            for (int half = 0; half < 2; half++) {
                int row = it * 16 + (lane >> 2) + half * 8;
                g_pd[(size_t)sy * NTOK * NHEAD + (size_t)(i0 + row) * NHEAD + h] = rsum[it * 2 + half];
            }
    }
    float* pn = g_pn + (size_t)sy * NTOK * 256;
#pragma unroll
    for (int it = 0; it < 2; it++)
#pragma unroll
        for (int n8 = 0; n8 < 4; n8++) {
            int r0 = i0 + it * 16 + (lane >> 2);
            int c = 32 * h + n8 * 8 + 2 * (lane & 3);
            *(float2*)(pn + (size_t)r0 * 256 + c) =
                make_float2(O[it][n8][0] * INV_PSCALE, O[it][n8][1] * INV_PSCALE);
            *(float2*)(pn + (size_t)(r0 + 8) * 256 + c) =
                make_float2(O[it][n8][2] * INV_PSCALE, O[it][n8][3] * INV_PSCALE);
        }
}

/* ================================================================= */
extern "C" void kernel_launch(void* const* d_in, const int* in_sizes, int n_in,
                              void* d_out, int out_size)
{
    const float* x    = (const float*)d_in[0];
    const float* pi   = (const float*)d_in[1];
    const float* tau  = (const float*)d_in[2];
    const float* adjs = (const float*)d_in[3];
    const float* Wq   = (const float*)d_in[4];
    const float* Wk   = (const float*)d_in[5];
    const float* Wv   = (const float*)d_in[6];
    const float* Wo   = (const float*)d_in[7];
    float* out = (float*)d_out;

    cudaFuncSetAttribute(attn_mma, cudaFuncAttributeMaxDynamicSharedMemorySize, SMEM_BYTES);

    gemm_qkv<<<dim3(4, 32, 3), 256>>>(x, Wq, Wk, Wv);
    attn_mma<<<dim3(NTOK / TIA, NSPL), 256, SMEM_BYTES>>>(pi, tau, adjs);
    gemm_out<<<dim3(4, 32), 256>>>(Wo, out);
}

// round 9
// speedup vs baseline: 1.3421x; 1.1828x over previous
#include <cuda_runtime.h>
#include <cuda_fp16.h>
#include <cstdint>

#define NTOK 2048
#define NHEAD 8
#define EPSV 1e-6f
#define QKSCALE 0.17677669529663687f
#define PSCALE 1024.0f
#define INV_PSCALE (1.0f / 1024.0f)
#define NSPL 4
#define JR (NTOK / NSPL)      /* 512 per split */
#define TIA 32
#define TJA 32
#define NJT (JR / TJA)        /* 16 tiles */
#define RSTRB 528             /* smem row stride bytes (264 fp16) */
#define PLANEB 16896          /* 32*528 */
#define BUFB 33792            /* 2 planes */
#define NX (NTOK * 256)       /* 524288 */

typedef unsigned long long ull;

__device__ float g_pn[NSPL * NTOK * 256];
__device__ float g_pd[NSPL * NTOK * NHEAD];
__device__ __align__(16) __half g_Qhl[2 * NX];
__device__ __align__(16) __half g_Khl[2 * NX];
__device__ __align__(16) __half g_Vhl[2 * NX];
__device__ __align__(16) __half g_Xhl[2 * NX];
__device__ __align__(16) __half g_Wqkv[3 * 2 * 256 * 256];

/* ---------------- f32x2 helpers (gemm_out) ---------------- */
__device__ __forceinline__ ull ffma2(ull a, ull b, ull c) {
    ull d; asm("fma.rn.f32x2 %0, %1, %2, %3;" : "=l"(d) : "l"(a), "l"(b), "l"(c)); return d;
}
__device__ __forceinline__ ull pack2(float lo, float hi) {
    ull r; asm("mov.b64 %0, {%1, %2};" : "=l"(r) : "f"(lo), "f"(hi)); return r;
}
__device__ __forceinline__ float2 unpack2(ull v) {
    float2 r; asm("mov.b64 {%0, %1}, %2;" : "=f"(r.x), "=f"(r.y) : "l"(v)); return r;
}

/* ---------------- warp-mma / async helpers ---------------- */
__device__ __forceinline__ uint32_t smem_u32(const void* p) {
    uint32_t a;
    asm("{ .reg .u64 t; cvta.to.shared.u64 t, %1; cvt.u32.u64 %0, t; }" : "=r"(a) : "l"(p));
    return a;
}
__device__ __forceinline__ void mma16816(float* d, const uint32_t* a, const uint32_t* b) {
    asm("mma.sync.aligned.m16n8k16.row.col.f32.f16.f16.f32 "
        "{%0,%1,%2,%3}, {%4,%5,%6,%7}, {%8,%9}, {%0,%1,%2,%3};"
        : "+f"(d[0]), "+f"(d[1]), "+f"(d[2]), "+f"(d[3])
        : "r"(a[0]), "r"(a[1]), "r"(a[2]), "r"(a[3]), "r"(b[0]), "r"(b[1]));
}
__device__ __forceinline__ void ldsm4(uint32_t* r, uint32_t a) {
    asm volatile("ldmatrix.sync.aligned.m8n8.x4.shared.b16 {%0,%1,%2,%3}, [%4];"
                 : "=r"(r[0]), "=r"(r[1]), "=r"(r[2]), "=r"(r[3]) : "r"(a));
}
__device__ __forceinline__ void ldsm2(uint32_t* r, uint32_t a) {
    asm volatile("ldmatrix.sync.aligned.m8n8.x2.shared.b16 {%0,%1}, [%2];"
                 : "=r"(r[0]), "=r"(r[1]) : "r"(a));
}
__device__ __forceinline__ void ldsm2t(uint32_t* r, uint32_t a) {
    asm volatile("ldmatrix.sync.aligned.m8n8.x2.trans.shared.b16 {%0,%1}, [%2];"
                 : "=r"(r[0]), "=r"(r[1]) : "r"(a));
}
__device__ __forceinline__ void cpa16(uint32_t d, const void* s) {
    asm volatile("cp.async.ca.shared.global [%0], [%1], 16;" :: "r"(d), "l"(s));
}
#define CP_COMMIT() asm volatile("cp.async.commit_group;" ::: "memory")
#define CP_WAIT1()  asm volatile("cp.async.wait_group 1;" ::: "memory")
#define CP_WAIT0()  asm volatile("cp.async.wait_group 0;" ::: "memory")
__device__ __forceinline__ void hiloh(float v, __half& h, __half& l) {
    h = __float2half_rn(v);
    l = __float2half_rn(v - __half2float(h));
}
__device__ __forceinline__ uint32_t packh(__half a, __half b) {
    return (uint32_t)*(unsigned short*)&a | ((uint32_t)*(unsigned short*)&b << 16);
}

/* =============== conv: x, Wq/Wk/Wv -> fp16 hi/lo planes =============== */
__global__ __launch_bounds__(256) void conv_inputs(const float* __restrict__ x,
                                                   const float* __restrict__ Wq,
                                                   const float* __restrict__ Wk,
                                                   const float* __restrict__ Wv)
{
    const int base = (blockIdx.x * 256 + threadIdx.x) * 4;
    float4 v;
    __half* dst;
    int stride;
    if (base < NX) {
        v = *(const float4*)(x + base);
        dst = g_Xhl + base;
        stride = NX;
    } else {
        int wrem = base - NX;
        int wi = wrem >> 16, rem = wrem & 65535;
        const float* W = (wi == 0) ? Wq : (wi == 1) ? Wk : Wv;
        v = *(const float4*)(W + rem);
        dst = g_Wqkv + wi * 131072 + rem;
        stride = 65536;
    }
    __half h0, l0, h1, l1, h2, l2, h3, l3;
    hiloh(v.x, h0, l0); hiloh(v.y, h1, l1); hiloh(v.z, h2, l2); hiloh(v.w, h3, l3);
    *(ull*)dst            = (ull)packh(h0, h1) | ((ull)packh(h2, h3) << 32);
    *(ull*)(dst + stride) = (ull)packh(l0, l1) | ((ull)packh(l2, l3) << 32);
}

/* =============== hgemm QKV: planes = (x @ W^T) in fp16 3-term =============== */
#define HPLANE 33792          /* 64*528 */
#define HSMEM  135168         /* 2 arrays x 2 planes x 33792 */

__global__ __launch_bounds__(256) void hgemm_qkv()
{
    extern __shared__ __align__(16) char hsm[];
    const uint32_t sA = smem_u32(hsm);
    const uint32_t sB = sA + 2 * HPLANE;

    const int t = threadIdx.x, lane = t & 31, w = t >> 5;
    const int i0 = blockIdx.y * 64;
    const int bn = blockIdx.x;            /* 0..11 */
    const int widx = bn >> 2;
    const int nw = (bn & 3) * 64;
    const __half* wsrc = g_Wqkv + widx * 131072 + nw * 256;

    /* load A (64x256, 2 planes) and B (64x256, 2 planes) */
    for (int c = t; c < 2048; c += 256) {
        int row = c >> 5, ch = c & 31;
        cpa16(sA + row * RSTRB + ch * 16,          g_Xhl + (size_t)(i0 + row) * 256 + ch * 8);
        cpa16(sA + HPLANE + row * RSTRB + ch * 16, g_Xhl + NX + (size_t)(i0 + row) * 256 + ch * 8);
        cpa16(sB + row * RSTRB + ch * 16,          wsrc + (size_t)row * 256 + ch * 8);
        cpa16(sB + HPLANE + row * RSTRB + ch * 16, wsrc + 65536 + (size_t)row * 256 + ch * 8);
    }
    CP_COMMIT(); CP_WAIT0();
    __syncthreads();

    const int mrow = (w >> 1) * 16;       /* 4 m-groups of 16 */
    const int ncol = (w & 1) * 32;        /* 2 n-groups of 32 */

    float acc[4][4];
#pragma unroll
    for (int n8 = 0; n8 < 4; n8++)
#pragma unroll
        for (int c = 0; c < 4; c++) acc[n8][c] = 0.f;

#pragma unroll 4
    for (int ks = 0; ks < 16; ks++) {
        uint32_t ah[4], al[4];
        {
            int row = mrow + (lane & 15);
            int col = ks * 16 + (lane >> 4) * 8;
            uint32_t ad = sA + row * RSTRB + col * 2;
            ldsm4(ah, ad);
            ldsm4(al, ad + HPLANE);
        }
#pragma unroll
        for (int n8 = 0; n8 < 4; n8++) {
            int row = ncol + n8 * 8 + (lane & 7);
            int col = ks * 16 + ((lane >> 3) & 1) * 8;
            uint32_t bd = sB + row * RSTRB + col * 2;
            uint32_t bh[2], bl[2];
            ldsm2(bh, bd);
            ldsm2(bl, bd + HPLANE);
            mma16816(acc[n8], ah, bh);
            mma16816(acc[n8], al, bh);
            mma16816(acc[n8], ah, bl);
        }
    }

    /* epilogue: hi/lo planes only */
    __half* P = (widx == 0) ? g_Qhl : (widx == 1) ? g_Khl : g_Vhl;
#pragma unroll
    for (int n8 = 0; n8 < 4; n8++) {
        int cg = nw + ncol + n8 * 8 + 2 * (lane & 3);
        int rg = i0 + mrow + (lane >> 2);
        __half h0, l0, h1, l1;
        hiloh(acc[n8][0], h0, l0); hiloh(acc[n8][1], h1, l1);
        *(uint32_t*)(P + (size_t)rg * 256 + cg) = packh(h0, h1);
        *(uint32_t*)(P + NX + (size_t)rg * 256 + cg) = packh(l0, l1);
        hiloh(acc[n8][2], h0, l0); hiloh(acc[n8][3], h1, l1);
        *(uint32_t*)(P + (size_t)(rg + 8) * 256 + cg) = packh(h0, h1);
        *(uint32_t*)(P + NX + (size_t)(rg + 8) * 256 + cg) = packh(l0, l1);
    }
}

/* =============== gemm_out: fp32 combine + x@Wo^T (measured-good) =============== */
__global__ __launch_bounds__(256) void gemm_out(const float* __restrict__ B,
                                                float* __restrict__ C)
{
    __shared__ __align__(16) float As[2][16][68];
    __shared__ __align__(16) float Bs[2][16][68];
    const int t = threadIdx.x, tx = t & 15, ty = t >> 4;
    const int bi = blockIdx.y, bj = blockIdx.x;
    const int row = t >> 2, k4 = (t & 3) * 4;
    const int arow = bi * 64 + row;
    const float* Bg = B + (size_t)(bj * 64 + row) * 256 + k4;

    auto loadA = [&](int c0) -> float4 {
        float4 n = *(const float4*)(g_pn + (size_t)arow * 256 + c0);
        float den = g_pd[arow * NHEAD + (c0 >> 5)];
#pragma unroll
        for (int s = 1; s < NSPL; s++) {
            float4 n2 = *(const float4*)(g_pn + (size_t)s * NTOK * 256 + (size_t)arow * 256 + c0);
            n.x += n2.x; n.y += n2.y; n.z += n2.z; n.w += n2.w;
            den += g_pd[s * NTOK * NHEAD + arow * NHEAD + (c0 >> 5)];
        }
        float inv = 1.0f / den;
        return make_float4(n.x * inv, n.y * inv, n.z * inv, n.w * inv);
    };

    float4 av = loadA(k4), bv = *(const float4*)Bg;
    As[0][k4 + 0][row] = av.x; As[0][k4 + 1][row] = av.y; As[0][k4 + 2][row] = av.z; As[0][k4 + 3][row] = av.w;
    Bs[0][k4 + 0][row] = bv.x; Bs[0][k4 + 1][row] = bv.y; Bs[0][k4 + 2][row] = bv.z; Bs[0][k4 + 3][row] = bv.w;
    __syncthreads();
    ull acc2[4][2];
#pragma unroll
    for (int r = 0; r < 4; r++) { acc2[r][0] = 0ull; acc2[r][1] = 0ull; }
    for (int kt = 0; kt < 16; kt++) {
        const int cur = kt & 1;
        if (kt < 15) { av = loadA((kt + 1) * 16 + k4); bv = *(const float4*)(Bg + (kt + 1) * 16); }
#pragma unroll
        for (int kk = 0; kk < 16; kk++) {
            float4 a = *(const float4*)&As[cur][kk][ty * 4];
            ull b0 = *(const ull*)&Bs[cur][kk][tx * 4];
            ull b1 = *(const ull*)&Bs[cur][kk][tx * 4 + 2];
            ull a0 = pack2(a.x, a.x); acc2[0][0] = ffma2(a0, b0, acc2[0][0]); acc2[0][1] = ffma2(a0, b1, acc2[0][1]);
            ull a1 = pack2(a.y, a.y); acc2[1][0] = ffma2(a1, b0, acc2[1][0]); acc2[1][1] = ffma2(a1, b1, acc2[1][1]);
            ull a2 = pack2(a.z, a.z); acc2[2][0] = ffma2(a2, b0, acc2[2][0]); acc2[2][1] = ffma2(a2, b1, acc2[2][1]);
            ull a3 = pack2(a.w, a.w); acc2[3][0] = ffma2(a3, b0, acc2[3][0]); acc2[3][1] = ffma2(a3, b1, acc2[3][1]);
        }
        if (kt < 15) {
            const int nx = cur ^ 1;
            As[nx][k4 + 0][row] = av.x; As[nx][k4 + 1][row] = av.y; As[nx][k4 + 2][row] = av.z; As[nx][k4 + 3][row] = av.w;
            Bs[nx][k4 + 0][row] = bv.x; Bs[nx][k4 + 1][row] = bv.y; Bs[nx][k4 + 2][row] = bv.z; Bs[nx][k4 + 3][row] = bv.w;
        }
        __syncthreads();
    }
#pragma unroll
    for (int r = 0; r < 4; r++) {
        float2 lo = unpack2(acc2[r][0]), hi = unpack2(acc2[r][1]);
        *(float4*)(C + (size_t)(bi * 64 + ty * 4 + r) * 256 + bj * 64 + tx * 4) =
            make_float4(lo.x, lo.y, hi.x, hi.y);
    }
}

/* =============== warp-mma attention (V hi-only PV) =============== */
#define OFF_K   0
#define OFF_V   (2 * BUFB)
#define OFF_W   (4 * BUFB)
#define OFF_PIT (OFF_W + 33792)
#define SMEM_BYTES (OFF_PIT + 4096)

__global__ __launch_bounds__(256) void attn_mma(
    const float* __restrict__ pi, const float* __restrict__ tau,
    const float* __restrict__ adjs)
{
    extern __shared__ __align__(16) char smraw[];
    const uint32_t sb = smem_u32(smraw);
    float* Ws   = (float*)(smraw + OFF_W);
    float* pits = (float*)(smraw + OFF_PIT);

    const int t = threadIdx.x, lane = t & 31, h = t >> 5;
    const int i0 = blockIdx.x * TIA;
    const int sy = blockIdx.y;
    const int jbase = sy * JR;
    const size_t NN = (size_t)NTOK * NTOK;

    for (int idx = t; idx < TIA * 32; idx += 256) {
        int hm = idx & 31;
        pits[idx] = tau[hm >> 2] * pi[(size_t)(i0 + (idx >> 5)) * 32 + hm];
    }

    /* ---- stage Q hi/lo planes into K buf0, pull A-fragments ---- */
#pragma unroll
    for (int k = 0; k < 8; k++) {
        int idx = t + k * 256;
        int plane = idx >> 10, r3 = idx & 1023, row = r3 >> 5, c16 = r3 & 31;
        const __half* s = g_Qhl + (size_t)plane * NX + (size_t)(i0 + row) * 256 + c16 * 8;
        ull v = *(const ull*)s, v2 = *(const ull*)(s + 4);
        char* d = smraw + OFF_K + plane * PLANEB + row * RSTRB + c16 * 16;
        *(ull*)d = v; *(ull*)(d + 8) = v2;
    }
    __syncthreads();
    uint32_t qh[2][2][4], ql[2][2][4];
#pragma unroll
    for (int it = 0; it < 2; it++)
#pragma unroll
        for (int ks = 0; ks < 2; ks++) {
            int row = it * 16 + (lane & 15);
            int col = 32 * h + ks * 16 + (lane >> 4) * 8;
            uint32_t a0 = sb + OFF_K + row * RSTRB + col * 2;
            ldsm4(qh[it][ks], a0);
            ldsm4(ql[it][ks], a0 + PLANEB);
        }
    __syncthreads();

    /* per-thread cp.async mapping: 12 chunks (Kh, Kl, Vh planes) */
    uint32_t cdst[12];
    const __half* csrc_base[12];
    int crow[12];
#pragma unroll
    for (int k = 0; k < 12; k++) {
        int idx = t + k * 256;
        int plane = idx >> 10, r3 = idx & 1023, row = r3 >> 5, c16 = r3 & 31;
        if (plane < 2) {
            cdst[k] = sb + OFF_K + plane * PLANEB + row * RSTRB + c16 * 16;
            csrc_base[k] = g_Khl + (size_t)plane * NX + c16 * 8;
        } else {
            cdst[k] = sb + OFF_V + row * RSTRB + c16 * 16;
            csrc_base[k] = g_Vhl + c16 * 8;
        }
        crow[k] = row;
    }

    /* prefetch tile 0 into buf 0 */
#pragma unroll
    for (int k = 0; k < 12; k++)
        cpa16(cdst[k], csrc_base[k] + (size_t)(jbase + crow[k]) * 256);
    CP_COMMIT();

    float O[2][4][4];
#pragma unroll
    for (int it = 0; it < 2; it++)
#pragma unroll
        for (int n8 = 0; n8 < 4; n8++)
#pragma unroll
            for (int c = 0; c < 4; c++) O[it][n8][c] = 0.f;
    float rsum[4] = {0.f, 0.f, 0.f, 0.f};

    const int wi = t >> 3;
    const int wj4 = (t & 7) * 4;

    for (int jt = 0; jt < NJT; jt++) {
        const int cur = jt & 1;
        const int j0 = jbase + jt * TJA;
        __syncthreads();

        const float* ab = adjs + (size_t)(i0 + wi) * NTOK + j0 + wj4;
        float4 a0 = *(const float4*)(ab);
        float4 a1 = *(const float4*)(ab + NN);
        float4 a2 = *(const float4*)(ab + 2 * NN);
        float4 a3 = *(const float4*)(ab + 3 * NN);

        if (jt + 1 < NJT) {
            const int jn = j0 + TJA;
            const uint32_t boff = (cur ^ 1) * BUFB;
#pragma unroll
            for (int k = 0; k < 12; k++)
                cpa16(cdst[k] + boff, csrc_base[k] + (size_t)(jn + crow[k]) * 256);
        }
        CP_COMMIT();

        {
            const float* pp = pits + wi * 32;
#pragma unroll
            for (int hh = 0; hh < NHEAD; hh++) {
                float p0 = pp[hh * 4 + 0], p1 = pp[hh * 4 + 1], p2 = pp[hh * 4 + 2], p3 = pp[hh * 4 + 3];
                float* wd = Ws + (hh * 32 + wi) * 33 + wj4;
                wd[0] = fmaf(p3, a3.x, fmaf(p2, a2.x, fmaf(p1, a1.x, fmaf(p0, a0.x, EPSV))));
                wd[1] = fmaf(p3, a3.y, fmaf(p2, a2.y, fmaf(p1, a1.y, fmaf(p0, a0.y, EPSV))));
                wd[2] = fmaf(p3, a3.z, fmaf(p2, a2.z, fmaf(p1, a1.z, fmaf(p0, a0.z, EPSV))));
                wd[3] = fmaf(p3, a3.w, fmaf(p2, a2.w, fmaf(p1, a1.w, fmaf(p0, a0.w, EPSV))));
            }
        }
        CP_WAIT1();
        __syncthreads();

        /* ---- QK^T: S = Qh*Kh + Ql*Kh ---- */
        float S[2][4][4];
#pragma unroll
        for (int it = 0; it < 2; it++)
#pragma unroll
            for (int j8 = 0; j8 < 4; j8++)
#pragma unroll
                for (int c = 0; c < 4; c++) S[it][j8][c] = 0.f;
        const uint32_t kbase = sb + OFF_K + cur * BUFB;
#pragma unroll
        for (int j8 = 0; j8 < 4; j8++)
#pragma unroll
            for (int ks = 0; ks < 2; ks++) {
                int krow = j8 * 8 + (lane & 7);
                int kcol = 32 * h + ks * 16 + ((lane >> 3) & 1) * 8;
                uint32_t ad = kbase + krow * RSTRB + kcol * 2;
                uint32_t bh[2];
                ldsm2(bh, ad);
#pragma unroll
                for (int it = 0; it < 2; it++) {
                    mma16816(S[it][j8], qh[it][ks], bh);
                    mma16816(S[it][j8], ql[it][ks], bh);
                }
            }

        /* ---- p = w * exp(s*scale); single fp16 P (scaled) ---- */
        uint32_t ph[2][2][4];
#pragma unroll
        for (int it = 0; it < 2; it++)
#pragma unroll
            for (int j8 = 0; j8 < 4; j8++) {
                int r0 = it * 16 + (lane >> 2);
                int c0 = j8 * 8 + 2 * (lane & 3);
                const float* wr0 = Ws + (h * 32 + r0) * 33 + c0;
                const float* wr1 = Ws + (h * 32 + r0 + 8) * 33 + c0;
                float p0 = wr0[0] * __expf(S[it][j8][0] * QKSCALE);
                float p1 = wr0[1] * __expf(S[it][j8][1] * QKSCALE);
                float p2 = wr1[0] * __expf(S[it][j8][2] * QKSCALE);
                float p3 = wr1[1] * __expf(S[it][j8][3] * QKSCALE);
                rsum[it * 2 + 0] += p0 + p1;
                rsum[it * 2 + 1] += p2 + p3;
                __half f0 = __float2half_rn(p0 * PSCALE);
                __half f1 = __float2half_rn(p1 * PSCALE);
                __half f2 = __float2half_rn(p2 * PSCALE);
                __half f3 = __float2half_rn(p3 * PSCALE);
                int kc = j8 >> 1, sl = (j8 & 1) * 2;
                ph[it][kc][sl + 0] = packh(f0, f1);
                ph[it][kc][sl + 1] = packh(f2, f3);
            }

        /* ---- O += P @ Vh ---- */
        const uint32_t vbase = sb + OFF_V + cur * BUFB;
#pragma unroll
        for (int n8 = 0; n8 < 4; n8++)
#pragma unroll
            for (int kc = 0; kc < 2; kc++) {
                int vrow = kc * 16 + (lane & 15);
                int vcol = 32 * h + n8 * 8;
                uint32_t ad = vbase + vrow * RSTRB + vcol * 2;
                uint32_t vh[2];
                ldsm2t(vh, ad);
#pragma unroll
                for (int it = 0; it < 2; it++)
                    mma16816(O[it][n8], ph[it][kc], vh);
            }
    }

    /* ---- epilogue ---- */
#pragma unroll
    for (int v = 0; v < 4; v++) {
        float x = rsum[v];
        x += __shfl_xor_sync(0xffffffffu, x, 1);
        x += __shfl_xor_sync(0xffffffffu, x, 2);
        rsum[v] = x;
    }
    if ((lane & 3) == 0) {
#pragma unroll
        for (int it = 0; it < 2; it++)
#pragma unroll
            for (int half = 0; half < 2; half++) {
                int row = it * 16 + (lane >> 2) + half * 8;
                g_pd[(size_t)sy * NTOK * NHEAD + (size_t)(i0 + row) * NHEAD + h] = rsum[it * 2 + half];
            }
    }
    float* pn = g_pn + (size_t)sy * NTOK * 256;
#pragma unroll
    for (int it = 0; it < 2; it++)
#pragma unroll
        for (int n8 = 0; n8 < 4; n8++) {
            int r0 = i0 + it * 16 + (lane >> 2);
            int c = 32 * h + n8 * 8 + 2 * (lane & 3);
            *(float2*)(pn + (size_t)r0 * 256 + c) =
                make_float2(O[it][n8][0] * INV_PSCALE, O[it][n8][1] * INV_PSCALE);
            *(float2*)(pn + (size_t)(r0 + 8) * 256 + c) =
                make_float2(O[it][n8][2] * INV_PSCALE, O[it][n8][3] * INV_PSCALE);
        }
}

/* ================================================================= */
extern "C" void kernel_launch(void* const* d_in, const int* in_sizes, int n_in,
                              void* d_out, int out_size)
{
    const float* x    = (const float*)d_in[0];
    const float* pi   = (const float*)d_in[1];
    const float* tau  = (const float*)d_in[2];
    const float* adjs = (const float*)d_in[3];
    const float* Wq   = (const float*)d_in[4];
    const float* Wk   = (const float*)d_in[5];
    const float* Wv   = (const float*)d_in[6];
    const float* Wo   = (const float*)d_in[7];
    float* out = (float*)d_out;

    cudaFuncSetAttribute(attn_mma, cudaFuncAttributeMaxDynamicSharedMemorySize, SMEM_BYTES);
    cudaFuncSetAttribute(hgemm_qkv, cudaFuncAttributeMaxDynamicSharedMemorySize, HSMEM);

    conv_inputs<<<704, 256>>>(x, Wq, Wk, Wv);
    hgemm_qkv<<<dim3(12, 32), 256, HSMEM>>>();
    attn_mma<<<dim3(NTOK / TIA, NSPL), 256, SMEM_BYTES>>>(pi, tau, adjs);
    gemm_out<<<dim3(4, 32), 256>>>(Wo, out);
}

// round 10
// speedup vs baseline: 1.6380x; 1.2204x over previous
#include <cuda_runtime.h>
#include <cuda_fp16.h>
#include <cstdint>

#define NTOK 2048
#define NHEAD 8
#define EPSV 1e-6f
#define QKSCALE 0.17677669529663687f
#define PSCALE 1024.0f
#define INV_PSCALE (1.0f / 1024.0f)
#define NSPL 4
#define JR (NTOK / NSPL)      /* 512 per split */
#define TIA 32
#define TJA 32
#define NJT (JR / TJA)        /* 16 tiles */
#define RSTRB 528             /* smem row stride bytes (264 fp16) */
#define PLANEB 16896          /* 32*528 */
#define NX (NTOK * 256)       /* 524288 */

typedef unsigned long long ull;

__device__ float g_pn[NSPL * NTOK * 256];
__device__ float g_pd[NSPL * NTOK * NHEAD];
__device__ __align__(16) __half g_Qhl[2 * NX];
__device__ __align__(16) __half g_Khl[2 * NX];
__device__ __align__(16) __half g_Vhl[2 * NX];
__device__ __align__(16) __half g_Xhl[2 * NX];
__device__ __align__(16) __half g_Wall[4 * 2 * 256 * 256];   /* Wq,Wk,Wv,Wo hi/lo */

/* ---------------- warp-mma / async helpers ---------------- */
__device__ __forceinline__ uint32_t smem_u32(const void* p) {
    uint32_t a;
    asm("{ .reg .u64 t; cvta.to.shared.u64 t, %1; cvt.u32.u64 %0, t; }" : "=r"(a) : "l"(p));
    return a;
}
__device__ __forceinline__ void mma16816(float* d, const uint32_t* a, const uint32_t* b) {
    asm("mma.sync.aligned.m16n8k16.row.col.f32.f16.f16.f32 "
        "{%0,%1,%2,%3}, {%4,%5,%6,%7}, {%8,%9}, {%0,%1,%2,%3};"
        : "+f"(d[0]), "+f"(d[1]), "+f"(d[2]), "+f"(d[3])
        : "r"(a[0]), "r"(a[1]), "r"(a[2]), "r"(a[3]), "r"(b[0]), "r"(b[1]));
}
__device__ __forceinline__ void ldsm4(uint32_t* r, uint32_t a) {
    asm volatile("ldmatrix.sync.aligned.m8n8.x4.shared.b16 {%0,%1,%2,%3}, [%4];"
                 : "=r"(r[0]), "=r"(r[1]), "=r"(r[2]), "=r"(r[3]) : "r"(a));
}
__device__ __forceinline__ void ldsm2(uint32_t* r, uint32_t a) {
    asm volatile("ldmatrix.sync.aligned.m8n8.x2.shared.b16 {%0,%1}, [%2];"
                 : "=r"(r[0]), "=r"(r[1]) : "r"(a));
}
__device__ __forceinline__ void ldsm2t(uint32_t* r, uint32_t a) {
    asm volatile("ldmatrix.sync.aligned.m8n8.x2.trans.shared.b16 {%0,%1}, [%2];"
                 : "=r"(r[0]), "=r"(r[1]) : "r"(a));
}
__device__ __forceinline__ void cpa16(uint32_t d, const void* s) {
    asm volatile("cp.async.ca.shared.global [%0], [%1], 16;" :: "r"(d), "l"(s));
}
#define CP_COMMIT() asm volatile("cp.async.commit_group;" ::: "memory")
#define CP_WAIT0()  asm volatile("cp.async.wait_group 0;" ::: "memory")
__device__ __forceinline__ void hiloh(float v, __half& h, __half& l) {
    h = __float2half_rn(v);
    l = __float2half_rn(v - __half2float(h));
}
__device__ __forceinline__ uint32_t packh(__half a, __half b) {
    return (uint32_t)*(unsigned short*)&a | ((uint32_t)*(unsigned short*)&b << 16);
}

/* =============== conv: x, Wq/Wk/Wv/Wo -> fp16 hi/lo planes =============== */
__global__ __launch_bounds__(256) void conv_inputs(const float* __restrict__ x,
                                                   const float* __restrict__ Wq,
                                                   const float* __restrict__ Wk,
                                                   const float* __restrict__ Wv,
                                                   const float* __restrict__ Wo)
{
    const int base = (blockIdx.x * 256 + threadIdx.x) * 4;
    float4 v;
    __half* dst;
    int stride;
    if (base < NX) {
        v = *(const float4*)(x + base);
        dst = g_Xhl + base;
        stride = NX;
    } else {
        int wrem = base - NX;
        int wi = wrem >> 16, rem = wrem & 65535;
        const float* W = (wi == 0) ? Wq : (wi == 1) ? Wk : (wi == 2) ? Wv : Wo;
        v = *(const float4*)(W + rem);
        dst = g_Wall + wi * 131072 + rem;
        stride = 65536;
    }
    __half h0, l0, h1, l1, h2, l2, h3, l3;
    hiloh(v.x, h0, l0); hiloh(v.y, h1, l1); hiloh(v.z, h2, l2); hiloh(v.w, h3, l3);
    *(ull*)dst            = (ull)packh(h0, h1) | ((ull)packh(h2, h3) << 32);
    *(ull*)(dst + stride) = (ull)packh(l0, l1) | ((ull)packh(l2, l3) << 32);
}

/* =============== hgemm QKV: planes = (x @ W^T) in fp16 3-term =============== */
#define HPLANE 33792          /* 64*528 */
#define HSMEM  135168

__global__ __launch_bounds__(256) void hgemm_qkv()
{
    extern __shared__ __align__(16) char hsm[];
    const uint32_t sA = smem_u32(hsm);
    const uint32_t sB = sA + 2 * HPLANE;

    const int t = threadIdx.x, lane = t & 31, w = t >> 5;
    const int i0 = blockIdx.y * 64;
    const int bn = blockIdx.x;            /* 0..11 */
    const int widx = bn >> 2;
    const int nw = (bn & 3) * 64;
    const __half* wsrc = g_Wall + widx * 131072 + nw * 256;

    for (int c = t; c < 2048; c += 256) {
        int row = c >> 5, ch = c & 31;
        cpa16(sA + row * RSTRB + ch * 16,          g_Xhl + (size_t)(i0 + row) * 256 + ch * 8);
        cpa16(sA + HPLANE + row * RSTRB + ch * 16, g_Xhl + NX + (size_t)(i0 + row) * 256 + ch * 8);
        cpa16(sB + row * RSTRB + ch * 16,          wsrc + (size_t)row * 256 + ch * 8);
        cpa16(sB + HPLANE + row * RSTRB + ch * 16, wsrc + 65536 + (size_t)row * 256 + ch * 8);
    }
    CP_COMMIT(); CP_WAIT0();
    __syncthreads();

    const int mrow = (w >> 1) * 16;
    const int ncol = (w & 1) * 32;

    float acc[4][4];
#pragma unroll
    for (int n8 = 0; n8 < 4; n8++)
#pragma unroll
        for (int c = 0; c < 4; c++) acc[n8][c] = 0.f;

#pragma unroll 4
    for (int ks = 0; ks < 16; ks++) {
        uint32_t ah[4], al[4];
        {
            int row = mrow + (lane & 15);
            int col = ks * 16 + (lane >> 4) * 8;
            uint32_t ad = sA + row * RSTRB + col * 2;
            ldsm4(ah, ad);
            ldsm4(al, ad + HPLANE);
        }
#pragma unroll
        for (int n8 = 0; n8 < 4; n8++) {
            int row = ncol + n8 * 8 + (lane & 7);
            int col = ks * 16 + ((lane >> 3) & 1) * 8;
            uint32_t bd = sB + row * RSTRB + col * 2;
            uint32_t bh[2], bl[2];
            ldsm2(bh, bd);
            ldsm2(bl, bd + HPLANE);
            mma16816(acc[n8], ah, bh);
            mma16816(acc[n8], al, bh);
            mma16816(acc[n8], ah, bl);
        }
    }

    __half* P = (widx == 0) ? g_Qhl : (widx == 1) ? g_Khl : g_Vhl;
#pragma unroll
    for (int n8 = 0; n8 < 4; n8++) {
        int cg = nw + ncol + n8 * 8 + 2 * (lane & 3);
        int rg = i0 + mrow + (lane >> 2);
        __half h0, l0, h1, l1;
        hiloh(acc[n8][0], h0, l0); hiloh(acc[n8][1], h1, l1);
        *(uint32_t*)(P + (size_t)rg * 256 + cg) = packh(h0, h1);
        *(uint32_t*)(P + NX + (size_t)rg * 256 + cg) = packh(l0, l1);
        hiloh(acc[n8][2], h0, l0); hiloh(acc[n8][3], h1, l1);
        *(uint32_t*)(P + (size_t)(rg + 8) * 256 + cg) = packh(h0, h1);
        *(uint32_t*)(P + NX + (size_t)(rg + 8) * 256 + cg) = packh(l0, l1);
    }
}

/* =============== hgemm OUT: combine partials, out = O @ Wo^T (fp16 3-term) =============== */
__global__ __launch_bounds__(256) void hgemm_out(float* __restrict__ out)
{
    extern __shared__ __align__(16) char hsm[];
    const uint32_t sA = smem_u32(hsm);
    const uint32_t sB = sA + 2 * HPLANE;

    const int t = threadIdx.x, lane = t & 31, w = t >> 5;
    const int i0 = blockIdx.y * 64;
    const int nw = blockIdx.x * 64;
    const __half* wsrc = g_Wall + 3 * 131072 + nw * 256;

    for (int c = t; c < 2048; c += 256) {
        int row = c >> 5, ch = c & 31;
        cpa16(sB + row * RSTRB + ch * 16,          wsrc + (size_t)row * 256 + ch * 8);
        cpa16(sB + HPLANE + row * RSTRB + ch * 16, wsrc + 65536 + (size_t)row * 256 + ch * 8);
    }
    CP_COMMIT();

    /* combine split partials -> normalized O -> fp16 hi/lo planes in smem */
    for (int idx = t; idx < 64 * 64; idx += 256) {
        int row = idx >> 6, c4 = idx & 63;
        int arow = i0 + row, c0 = c4 * 4;
        float4 n = *(const float4*)(g_pn + (size_t)arow * 256 + c0);
        float den = g_pd[arow * NHEAD + (c0 >> 5)];
#pragma unroll
        for (int s = 1; s < NSPL; s++) {
            float4 n2 = *(const float4*)(g_pn + (size_t)s * NTOK * 256 + (size_t)arow * 256 + c0);
            n.x += n2.x; n.y += n2.y; n.z += n2.z; n.w += n2.w;
            den += g_pd[s * NTOK * NHEAD + arow * NHEAD + (c0 >> 5)];
        }
        float inv = 1.0f / den;
        __half h0, l0, h1, l1, h2, l2, h3, l3;
        hiloh(n.x * inv, h0, l0); hiloh(n.y * inv, h1, l1);
        hiloh(n.z * inv, h2, l2); hiloh(n.w * inv, h3, l3);
        char* d = hsm + row * RSTRB + c0 * 2;
        *(ull*)d = (ull)packh(h0, h1) | ((ull)packh(h2, h3) << 32);
        *(ull*)(d + HPLANE) = (ull)packh(l0, l1) | ((ull)packh(l2, l3) << 32);
    }
    CP_WAIT0();
    __syncthreads();

    const int mrow = (w >> 1) * 16;
    const int ncol = (w & 1) * 32;

    float acc[4][4];
#pragma unroll
    for (int n8 = 0; n8 < 4; n8++)
#pragma unroll
        for (int c = 0; c < 4; c++) acc[n8][c] = 0.f;

#pragma unroll 4
    for (int ks = 0; ks < 16; ks++) {
        uint32_t ah[4], al[4];
        {
            int row = mrow + (lane & 15);
            int col = ks * 16 + (lane >> 4) * 8;
            uint32_t ad = sA + row * RSTRB + col * 2;
            ldsm4(ah, ad);
            ldsm4(al, ad + HPLANE);
        }
#pragma unroll
        for (int n8 = 0; n8 < 4; n8++) {
            int row = ncol + n8 * 8 + (lane & 7);
            int col = ks * 16 + ((lane >> 3) & 1) * 8;
            uint32_t bd = sB + row * RSTRB + col * 2;
            uint32_t bh[2], bl[2];
            ldsm2(bh, bd);
            ldsm2(bl, bd + HPLANE);
            mma16816(acc[n8], ah, bh);
            mma16816(acc[n8], al, bh);
            mma16816(acc[n8], ah, bl);
        }
    }

#pragma unroll
    for (int n8 = 0; n8 < 4; n8++) {
        int cg = nw + ncol + n8 * 8 + 2 * (lane & 3);
        int rg = i0 + mrow + (lane >> 2);
        *(float2*)(out + (size_t)rg * 256 + cg) = make_float2(acc[n8][0], acc[n8][1]);
        *(float2*)(out + (size_t)(rg + 8) * 256 + cg) = make_float2(acc[n8][2], acc[n8][3]);
    }
}

/* =============== warp-mma attention: single buffer, 2 CTAs/SM =============== */
#define OFF_K   0                       /* 2 planes: 33792 */
#define OFF_V   (2 * PLANEB)            /* 1 plane: 16896 */
#define OFF_W   (3 * PLANEB)            /* float Ws[8][32][33] = 33792 */
#define OFF_PIT (OFF_W + 33792)         /* 4096 */
#define SMEM_BYTES (OFF_PIT + 4096)     /* 88576 */

__global__ __launch_bounds__(256, 2) void attn_mma(
    const float* __restrict__ pi, const float* __restrict__ tau,
    const float* __restrict__ adjs)
{
    extern __shared__ __align__(16) char smraw[];
    const uint32_t sb = smem_u32(smraw);
    float* Ws   = (float*)(smraw + OFF_W);
    float* pits = (float*)(smraw + OFF_PIT);

    const int t = threadIdx.x, lane = t & 31, h = t >> 5;
    const int i0 = blockIdx.x * TIA;
    const int sy = blockIdx.y;
    const int jbase = sy * JR;
    const size_t NN = (size_t)NTOK * NTOK;

    for (int idx = t; idx < TIA * 32; idx += 256) {
        int hm = idx & 31;
        pits[idx] = tau[hm >> 2] * pi[(size_t)(i0 + (idx >> 5)) * 32 + hm];
    }

    /* ---- stage Q hi/lo planes into K buffer, pull A-fragments ---- */
#pragma unroll
    for (int k = 0; k < 8; k++) {
        int idx = t + k * 256;
        int plane = idx >> 10, r3 = idx & 1023, row = r3 >> 5, c16 = r3 & 31;
        const __half* s = g_Qhl + (size_t)plane * NX + (size_t)(i0 + row) * 256 + c16 * 8;
        ull v = *(const ull*)s, v2 = *(const ull*)(s + 4);
        char* d = smraw + OFF_K + plane * PLANEB + row * RSTRB + c16 * 16;
        *(ull*)d = v; *(ull*)(d + 8) = v2;
    }
    __syncthreads();
    uint32_t qh[2][2][4], ql[2][2][4];
#pragma unroll
    for (int it = 0; it < 2; it++)
#pragma unroll
        for (int ks = 0; ks < 2; ks++) {
            int row = it * 16 + (lane & 15);
            int col = 32 * h + ks * 16 + (lane >> 4) * 8;
            uint32_t a0 = sb + OFF_K + row * RSTRB + col * 2;
            ldsm4(qh[it][ks], a0);
            ldsm4(ql[it][ks], a0 + PLANEB);
        }

    /* per-thread cp.async mapping: 12 chunks (Kh, Kl, Vh planes) */
    uint32_t cdst[12];
    const __half* csrc_base[12];
    int crow[12];
#pragma unroll
    for (int k = 0; k < 12; k++) {
        int idx = t + k * 256;
        int plane = idx >> 10, r3 = idx & 1023, row = r3 >> 5, c16 = r3 & 31;
        if (plane < 2) {
            cdst[k] = sb + OFF_K + plane * PLANEB + row * RSTRB + c16 * 16;
            csrc_base[k] = g_Khl + (size_t)plane * NX + c16 * 8;
        } else {
            cdst[k] = sb + OFF_V + row * RSTRB + c16 * 16;
            csrc_base[k] = g_Vhl + c16 * 8;
        }
        crow[k] = row;
    }

    float O[2][4][4];
#pragma unroll
    for (int it = 0; it < 2; it++)
#pragma unroll
        for (int n8 = 0; n8 < 4; n8++)
#pragma unroll
            for (int c = 0; c < 4; c++) O[it][n8][c] = 0.f;
    float rsum[4] = {0.f, 0.f, 0.f, 0.f};

    const int wi = t >> 3;
    const int wj4 = (t & 7) * 4;

    for (int jt = 0; jt < NJT; jt++) {
        const int j0 = jbase + jt * TJA;
        __syncthreads();   /* all reads of previous tile done */

        /* issue this tile's K/V loads */
#pragma unroll
        for (int k = 0; k < 12; k++)
            cpa16(cdst[k], csrc_base[k] + (size_t)(j0 + crow[k]) * 256);
        CP_COMMIT();

        /* adjs loads + graph weights (overlap the cp.async) */
        const float* ab = adjs + (size_t)(i0 + wi) * NTOK + j0 + wj4;
        float4 a0 = *(const float4*)(ab);
        float4 a1 = *(const float4*)(ab + NN);
        float4 a2 = *(const float4*)(ab + 2 * NN);
        float4 a3 = *(const float4*)(ab + 3 * NN);
        {
            const float* pp = pits + wi * 32;
#pragma unroll
            for (int hh = 0; hh < NHEAD; hh++) {
                float p0 = pp[hh * 4 + 0], p1 = pp[hh * 4 + 1], p2 = pp[hh * 4 + 2], p3 = pp[hh * 4 + 3];
                float* wd = Ws + (hh * 32 + wi) * 33 + wj4;
                wd[0] = fmaf(p3, a3.x, fmaf(p2, a2.x, fmaf(p1, a1.x, fmaf(p0, a0.x, EPSV))));
                wd[1] = fmaf(p3, a3.y, fmaf(p2, a2.y, fmaf(p1, a1.y, fmaf(p0, a0.y, EPSV))));
                wd[2] = fmaf(p3, a3.z, fmaf(p2, a2.z, fmaf(p1, a1.z, fmaf(p0, a0.z, EPSV))));
                wd[3] = fmaf(p3, a3.w, fmaf(p2, a2.w, fmaf(p1, a1.w, fmaf(p0, a0.w, EPSV))));
            }
        }
        CP_WAIT0();
        __syncthreads();

        /* ---- QK^T: S = Qh*Kh + Ql*Kh ---- */
        float S[2][4][4];
#pragma unroll
        for (int it = 0; it < 2; it++)
#pragma unroll
            for (int j8 = 0; j8 < 4; j8++)
#pragma unroll
                for (int c = 0; c < 4; c++) S[it][j8][c] = 0.f;
        const uint32_t kbase = sb + OFF_K;
#pragma unroll
        for (int j8 = 0; j8 < 4; j8++)
#pragma unroll
            for (int ks = 0; ks < 2; ks++) {
                int krow = j8 * 8 + (lane & 7);
                int kcol = 32 * h + ks * 16 + ((lane >> 3) & 1) * 8;
                uint32_t ad = kbase + krow * RSTRB + kcol * 2;
                uint32_t bh[2];
                ldsm2(bh, ad);
#pragma unroll
                for (int it = 0; it < 2; it++) {
                    mma16816(S[it][j8], qh[it][ks], bh);
                    mma16816(S[it][j8], ql[it][ks], bh);
                }
            }

        /* ---- p = w * exp(s*scale); single fp16 P (scaled) ---- */
        uint32_t ph[2][2][4];
#pragma unroll
        for (int it = 0; it < 2; it++)
#pragma unroll
            for (int j8 = 0; j8 < 4; j8++) {
                int r0 = it * 16 + (lane >> 2);
                int c0 = j8 * 8 + 2 * (lane & 3);
                const float* wr0 = Ws + (h * 32 + r0) * 33 + c0;
                const float* wr1 = Ws + (h * 32 + r0 + 8) * 33 + c0;
                float p0 = wr0[0] * __expf(S[it][j8][0] * QKSCALE);
                float p1 = wr0[1] * __expf(S[it][j8][1] * QKSCALE);
                float p2 = wr1[0] * __expf(S[it][j8][2] * QKSCALE);
                float p3 = wr1[1] * __expf(S[it][j8][3] * QKSCALE);
                rsum[it * 2 + 0] += p0 + p1;
                rsum[it * 2 + 1] += p2 + p3;
                __half f0 = __float2half_rn(p0 * PSCALE);
                __half f1 = __float2half_rn(p1 * PSCALE);
                __half f2 = __float2half_rn(p2 * PSCALE);
                __half f3 = __float2half_rn(p3 * PSCALE);
                int kc = j8 >> 1, sl = (j8 & 1) * 2;
                ph[it][kc][sl + 0] = packh(f0, f1);
                ph[it][kc][sl + 1] = packh(f2, f3);
            }

        /* ---- O += P @ Vh ---- */
        const uint32_t vbase = sb + OFF_V;
#pragma unroll
        for (int n8 = 0; n8 < 4; n8++)
#pragma unroll
            for (int kc = 0; kc < 2; kc++) {
                int vrow = kc * 16 + (lane & 15);
                int vcol = 32 * h + n8 * 8;
                uint32_t ad = vbase + vrow * RSTRB + vcol * 2;
                uint32_t vh[2];
                ldsm2t(vh, ad);
#pragma unroll
                for (int it = 0; it < 2; it++)
                    mma16816(O[it][n8], ph[it][kc], vh);
            }
    }

    /* ---- epilogue ---- */
#pragma unroll
    for (int v = 0; v < 4; v++) {
        float x = rsum[v];
        x += __shfl_xor_sync(0xffffffffu, x, 1);
        x += __shfl_xor_sync(0xffffffffu, x, 2);
        rsum[v] = x;
    }
    if ((lane & 3) == 0) {
#pragma unroll
        for (int it = 0; it < 2; it++)
#pragma unroll
            for (int half = 0; half < 2; half++) {
                int row = it * 16 + (lane >> 2) + half * 8;
                g_pd[(size_t)sy * NTOK * NHEAD + (size_t)(i0 + row) * NHEAD + h] = rsum[it * 2 + half];
            }
    }
    float* pn = g_pn + (size_t)sy * NTOK * 256;
#pragma unroll
    for (int it = 0; it < 2; it++)
#pragma unroll
        for (int n8 = 0; n8 < 4; n8++) {
            int r0 = i0 + it * 16 + (lane >> 2);
            int c = 32 * h + n8 * 8 + 2 * (lane & 3);
            *(float2*)(pn + (size_t)r0 * 256 + c) =
                make_float2(O[it][n8][0] * INV_PSCALE, O[it][n8][1] * INV_PSCALE);
            *(float2*)(pn + (size_t)(r0 + 8) * 256 + c) =
                make_float2(O[it][n8][2] * INV_PSCALE, O[it][n8][3] * INV_PSCALE);
        }
}

/* ================================================================= */
extern "C" void kernel_launch(void* const* d_in, const int* in_sizes, int n_in,
                              void* d_out, int out_size)
{
    const float* x    = (const float*)d_in[0];
    const float* pi   = (const float*)d_in[1];
    const float* tau  = (const float*)d_in[2];
    const float* adjs = (const float*)d_in[3];
    const float* Wq   = (const float*)d_in[4];
    const float* Wk   = (const float*)d_in[5];
    const float* Wv   = (const float*)d_in[6];
    const float* Wo   = (const float*)d_in[7];
    float* out = (float*)d_out;

    cudaFuncSetAttribute(attn_mma, cudaFuncAttributeMaxDynamicSharedMemorySize, SMEM_BYTES);
    cudaFuncSetAttribute(hgemm_qkv, cudaFuncAttributeMaxDynamicSharedMemorySize, HSMEM);
    cudaFuncSetAttribute(hgemm_out, cudaFuncAttributeMaxDynamicSharedMemorySize, HSMEM);

    conv_inputs<<<768, 256>>>(x, Wq, Wk, Wv, Wo);
    hgemm_qkv<<<dim3(12, 32), 256, HSMEM>>>();
    attn_mma<<<dim3(NTOK / TIA, NSPL), 256, SMEM_BYTES>>>(pi, tau, adjs);
    hgemm_out<<<dim3(4, 32), 256, HSMEM>>>(out);
}

// round 11
// speedup vs baseline: 1.9732x; 1.2046x over previous
#include <cuda_runtime.h>
#include <cuda_fp16.h>
#include <cstdint>

#define NTOK 2048
#define NHEAD 8
#define EPSV 1e-6f
#define QKSCALE 0.17677669529663687f
#define PSCALE 1024.0f
#define INV_PSCALE (1.0f / 1024.0f)
#define NSPL 4
#define JR (NTOK / NSPL)      /* 512 per split */
#define TIA 32
#define TJA 32
#define NJT (JR / TJA)        /* 16 tiles */
#define RSTRB 528             /* smem row stride bytes (264 fp16) */
#define PLANEB 16896          /* 32*528 */
#define NX (NTOK * 256)       /* 524288 */

typedef unsigned long long ull;

__device__ float g_pn[NSPL * NTOK * 256];
__device__ float g_pd[NSPL * NTOK * NHEAD];
__device__ __align__(16) __half g_Qhl[2 * NX];
__device__ __align__(16) __half g_Khl[2 * NX];
__device__ __align__(16) __half g_Vhl[2 * NX];
__device__ __align__(16) __half g_Xhl[2 * NX];    /* x planes; reused as O planes */
__device__ __align__(16) __half g_Wall[4 * 2 * 256 * 256];

/* ---------------- warp-mma / async helpers ---------------- */
__device__ __forceinline__ uint32_t smem_u32(const void* p) {
    uint32_t a;
    asm("{ .reg .u64 t; cvta.to.shared.u64 t, %1; cvt.u32.u64 %0, t; }" : "=r"(a) : "l"(p));
    return a;
}
__device__ __forceinline__ void mma16816(float* d, const uint32_t* a, const uint32_t* b) {
    asm("mma.sync.aligned.m16n8k16.row.col.f32.f16.f16.f32 "
        "{%0,%1,%2,%3}, {%4,%5,%6,%7}, {%8,%9}, {%0,%1,%2,%3};"
        : "+f"(d[0]), "+f"(d[1]), "+f"(d[2]), "+f"(d[3])
        : "r"(a[0]), "r"(a[1]), "r"(a[2]), "r"(a[3]), "r"(b[0]), "r"(b[1]));
}
__device__ __forceinline__ void ldsm4(uint32_t* r, uint32_t a) {
    asm volatile("ldmatrix.sync.aligned.m8n8.x4.shared.b16 {%0,%1,%2,%3}, [%4];"
                 : "=r"(r[0]), "=r"(r[1]), "=r"(r[2]), "=r"(r[3]) : "r"(a));
}
__device__ __forceinline__ void ldsm2(uint32_t* r, uint32_t a) {
    asm volatile("ldmatrix.sync.aligned.m8n8.x2.shared.b16 {%0,%1}, [%2];"
                 : "=r"(r[0]), "=r"(r[1]) : "r"(a));
}
__device__ __forceinline__ void ldsm2t(uint32_t* r, uint32_t a) {
    asm volatile("ldmatrix.sync.aligned.m8n8.x2.trans.shared.b16 {%0,%1}, [%2];"
                 : "=r"(r[0]), "=r"(r[1]) : "r"(a));
}
__device__ __forceinline__ void cpa16(uint32_t d, const void* s) {
    asm volatile("cp.async.ca.shared.global [%0], [%1], 16;" :: "r"(d), "l"(s));
}
#define CP_COMMIT() asm volatile("cp.async.commit_group;" ::: "memory")
#define CP_WAIT0()  asm volatile("cp.async.wait_group 0;" ::: "memory")
__device__ __forceinline__ void hiloh(float v, __half& h, __half& l) {
    h = __float2half_rn(v);
    l = __float2half_rn(v - __half2float(h));
}
__device__ __forceinline__ uint32_t packh(__half a, __half b) {
    return (uint32_t)*(unsigned short*)&a | ((uint32_t)*(unsigned short*)&b << 16);
}

/* =============== conv: x, Wq/Wk/Wv/Wo -> fp16 hi/lo planes =============== */
__global__ __launch_bounds__(256) void conv_inputs(const float* __restrict__ x,
                                                   const float* __restrict__ Wq,
                                                   const float* __restrict__ Wk,
                                                   const float* __restrict__ Wv,
                                                   const float* __restrict__ Wo)
{
    const int base = (blockIdx.x * 256 + threadIdx.x) * 4;
    float4 v;
    __half* dst;
    int stride;
    if (base < NX) {
        v = *(const float4*)(x + base);
        dst = g_Xhl + base;
        stride = NX;
    } else {
        int wrem = base - NX;
        int wi = wrem >> 16, rem = wrem & 65535;
        const float* W = (wi == 0) ? Wq : (wi == 1) ? Wk : (wi == 2) ? Wv : Wo;
        v = *(const float4*)(W + rem);
        dst = g_Wall + wi * 131072 + rem;
        stride = 65536;
    }
    __half h0, l0, h1, l1, h2, l2, h3, l3;
    hiloh(v.x, h0, l0); hiloh(v.y, h1, l1); hiloh(v.z, h2, l2); hiloh(v.w, h3, l3);
    *(ull*)dst            = (ull)packh(h0, h1) | ((ull)packh(h2, h3) << 32);
    *(ull*)(dst + stride) = (ull)packh(l0, l1) | ((ull)packh(l2, l3) << 32);
}

/* =============== hgemm body: planes/out = (A_planes @ W^T), fp16 3-term =============== */
#define HPLANE 33792          /* 64*528 */
#define HSMEM  135168

template<bool TO_PLANES>
__device__ __forceinline__ void hgemm_body(const __half* __restrict__ Asrc,
                                           const __half* __restrict__ wsrc,
                                           __half* __restrict__ Pdst,
                                           float* __restrict__ Fdst,
                                           int i0, int nw)
{
    extern __shared__ __align__(16) char hsm[];
    const uint32_t sA = smem_u32(hsm);
    const uint32_t sB = sA + 2 * HPLANE;

    const int t = threadIdx.x, lane = t & 31, w = t >> 5;

    for (int c = t; c < 2048; c += 256) {
        int row = c >> 5, ch = c & 31;
        cpa16(sA + row * RSTRB + ch * 16,          Asrc + (size_t)(i0 + row) * 256 + ch * 8);
        cpa16(sA + HPLANE + row * RSTRB + ch * 16, Asrc + NX + (size_t)(i0 + row) * 256 + ch * 8);
        cpa16(sB + row * RSTRB + ch * 16,          wsrc + (size_t)row * 256 + ch * 8);
        cpa16(sB + HPLANE + row * RSTRB + ch * 16, wsrc + 65536 + (size_t)row * 256 + ch * 8);
    }
    CP_COMMIT(); CP_WAIT0();
    __syncthreads();

    const int mrow = (w >> 1) * 16;
    const int ncol = (w & 1) * 32;

    float acc[4][4];
#pragma unroll
    for (int n8 = 0; n8 < 4; n8++)
#pragma unroll
        for (int c = 0; c < 4; c++) acc[n8][c] = 0.f;

#pragma unroll 4
    for (int ks = 0; ks < 16; ks++) {
        uint32_t ah[4], al[4];
        {
            int row = mrow + (lane & 15);
            int col = ks * 16 + (lane >> 4) * 8;
            uint32_t ad = sA + row * RSTRB + col * 2;
            ldsm4(ah, ad);
            ldsm4(al, ad + HPLANE);
        }
#pragma unroll
        for (int n8 = 0; n8 < 4; n8++) {
            int row = ncol + n8 * 8 + (lane & 7);
            int col = ks * 16 + ((lane >> 3) & 1) * 8;
            uint32_t bd = sB + row * RSTRB + col * 2;
            uint32_t bh[2], bl[2];
            ldsm2(bh, bd);
            ldsm2(bl, bd + HPLANE);
            mma16816(acc[n8], ah, bh);
            mma16816(acc[n8], al, bh);
            mma16816(acc[n8], ah, bl);
        }
    }

#pragma unroll
    for (int n8 = 0; n8 < 4; n8++) {
        int cg = nw + ncol + n8 * 8 + 2 * (lane & 3);
        int rg = i0 + mrow + (lane >> 2);
        if (TO_PLANES) {
            __half h0, l0, h1, l1;
            hiloh(acc[n8][0], h0, l0); hiloh(acc[n8][1], h1, l1);
            *(uint32_t*)(Pdst + (size_t)rg * 256 + cg) = packh(h0, h1);
            *(uint32_t*)(Pdst + NX + (size_t)rg * 256 + cg) = packh(l0, l1);
            hiloh(acc[n8][2], h0, l0); hiloh(acc[n8][3], h1, l1);
            *(uint32_t*)(Pdst + (size_t)(rg + 8) * 256 + cg) = packh(h0, h1);
            *(uint32_t*)(Pdst + NX + (size_t)(rg + 8) * 256 + cg) = packh(l0, l1);
        } else {
            *(float2*)(Fdst + (size_t)rg * 256 + cg) = make_float2(acc[n8][0], acc[n8][1]);
            *(float2*)(Fdst + (size_t)(rg + 8) * 256 + cg) = make_float2(acc[n8][2], acc[n8][3]);
        }
    }
}

__global__ __launch_bounds__(256) void hgemm_qkv()
{
    const int bn = blockIdx.x;            /* 0..11 */
    const int widx = bn >> 2;
    const int nw = (bn & 3) * 64;
    __half* P = (widx == 0) ? g_Qhl : (widx == 1) ? g_Khl : g_Vhl;
    hgemm_body<true>(g_Xhl, g_Wall + widx * 131072 + nw * 256, P, nullptr,
                     blockIdx.y * 64, nw);
}

__global__ __launch_bounds__(256) void hgemm_out(float* __restrict__ out)
{
    const int nw = blockIdx.x * 64;
    hgemm_body<false>(g_Xhl, g_Wall + 3 * 131072 + nw * 256, nullptr, out,
                      blockIdx.y * 64, nw);
}

/* =============== combine_o: fold split partials -> O fp16 planes (reuse g_Xhl) =============== */
__global__ __launch_bounds__(256) void combine_o()
{
    const int idx4 = blockIdx.x * 256 + threadIdx.x;   /* 0..131071 */
    const int row = idx4 >> 6;
    const int c0 = (idx4 & 63) * 4;
    float4 n = *(const float4*)(g_pn + (size_t)row * 256 + c0);
    float den = g_pd[row * NHEAD + (c0 >> 5)];
#pragma unroll
    for (int s = 1; s < NSPL; s++) {
        float4 n2 = *(const float4*)(g_pn + (size_t)s * NTOK * 256 + (size_t)row * 256 + c0);
        n.x += n2.x; n.y += n2.y; n.z += n2.z; n.w += n2.w;
        den += g_pd[s * NTOK * NHEAD + row * NHEAD + (c0 >> 5)];
    }
    float inv = 1.0f / den;
    __half h0, l0, h1, l1, h2, l2, h3, l3;
    hiloh(n.x * inv, h0, l0); hiloh(n.y * inv, h1, l1);
    hiloh(n.z * inv, h2, l2); hiloh(n.w * inv, h3, l3);
    __half* d = g_Xhl + (size_t)row * 256 + c0;
    *(ull*)d        = (ull)packh(h0, h1) | ((ull)packh(h2, h3) << 32);
    *(ull*)(d + NX) = (ull)packh(l0, l1) | ((ull)packh(l2, l3) << 32);
}

/* =============== warp-mma attention: Qh-only QK, Kh/Vh tiles, 2 CTAs/SM =============== */
#define OFF_K   0                       /* 1 plane: 16896 */
#define OFF_V   PLANEB                  /* 1 plane: 16896 */
#define OFF_W   (2 * PLANEB)            /* float Ws[8][32][33] = 33792 */
#define OFF_PIT (OFF_W + 33792)         /* 4096 */
#define SMEM_BYTES (OFF_PIT + 4096)     /* 71680 */

__global__ __launch_bounds__(256, 2) void attn_mma(
    const float* __restrict__ pi, const float* __restrict__ tau,
    const float* __restrict__ adjs)
{
    extern __shared__ __align__(16) char smraw[];
    const uint32_t sb = smem_u32(smraw);
    float* Ws   = (float*)(smraw + OFF_W);
    float* pits = (float*)(smraw + OFF_PIT);

    const int t = threadIdx.x, lane = t & 31, h = t >> 5;
    const int i0 = blockIdx.x * TIA;
    const int sy = blockIdx.y;
    const int jbase = sy * JR;
    const size_t NN = (size_t)NTOK * NTOK;

    for (int idx = t; idx < TIA * 32; idx += 256) {
        int hm = idx & 31;
        pits[idx] = tau[hm >> 2] * pi[(size_t)(i0 + (idx >> 5)) * 32 + hm];
    }

    /* ---- stage Q hi plane into K buffer, pull A-fragments ---- */
#pragma unroll
    for (int k = 0; k < 4; k++) {
        int idx = t + k * 256;              /* 1024 chunks of 16B */
        int row = idx >> 5, c16 = idx & 31;
        const __half* s = g_Qhl + (size_t)(i0 + row) * 256 + c16 * 8;
        ull v = *(const ull*)s, v2 = *(const ull*)(s + 4);
        char* d = smraw + OFF_K + row * RSTRB + c16 * 16;
        *(ull*)d = v; *(ull*)(d + 8) = v2;
    }
    __syncthreads();
    uint32_t qh[2][2][4];
#pragma unroll
    for (int it = 0; it < 2; it++)
#pragma unroll
        for (int ks = 0; ks < 2; ks++) {
            int row = it * 16 + (lane & 15);
            int col = 32 * h + ks * 16 + (lane >> 4) * 8;
            ldsm4(qh[it][ks], sb + OFF_K + row * RSTRB + col * 2);
        }

    /* per-thread cp.async mapping: 8 chunks (Kh, Vh planes) */
    uint32_t cdst[8];
    const __half* csrc_base[8];
    int crow[8];
#pragma unroll
    for (int k = 0; k < 8; k++) {
        int idx = t + k * 256;              /* 2048: plane(K/V) x row x c16 */
        int plane = idx >> 10, r3 = idx & 1023, row = r3 >> 5, c16 = r3 & 31;
        cdst[k] = sb + (plane ? OFF_V : OFF_K) + row * RSTRB + c16 * 16;
        csrc_base[k] = (plane ? g_Vhl : g_Khl) + c16 * 8;
        crow[k] = row;
    }

    float O[2][4][4];
#pragma unroll
    for (int it = 0; it < 2; it++)
#pragma unroll
        for (int n8 = 0; n8 < 4; n8++)
#pragma unroll
            for (int c = 0; c < 4; c++) O[it][n8][c] = 0.f;
    float rsum[4] = {0.f, 0.f, 0.f, 0.f};

    const int wi = t >> 3;
    const int wj4 = (t & 7) * 4;

    for (int jt = 0; jt < NJT; jt++) {
        const int j0 = jbase + jt * TJA;
        __syncthreads();   /* reads of previous tile (and Q fragments) done */

        /* issue this tile's K/V loads */
#pragma unroll
        for (int k = 0; k < 8; k++)
            cpa16(cdst[k], csrc_base[k] + (size_t)(j0 + crow[k]) * 256);
        CP_COMMIT();

        /* adjs loads + graph weights (overlap the cp.async) */
        const float* ab = adjs + (size_t)(i0 + wi) * NTOK + j0 + wj4;
        float4 a0 = *(const float4*)(ab);
        float4 a1 = *(const float4*)(ab + NN);
        float4 a2 = *(const float4*)(ab + 2 * NN);
        float4 a3 = *(const float4*)(ab + 3 * NN);
        {
            const float* pp = pits + wi * 32;
#pragma unroll
            for (int hh = 0; hh < NHEAD; hh++) {
                float p0 = pp[hh * 4 + 0], p1 = pp[hh * 4 + 1], p2 = pp[hh * 4 + 2], p3 = pp[hh * 4 + 3];
                float* wd = Ws + (hh * 32 + wi) * 33 + wj4;
                wd[0] = fmaf(p3, a3.x, fmaf(p2, a2.x, fmaf(p1, a1.x, fmaf(p0, a0.x, EPSV))));
                wd[1] = fmaf(p3, a3.y, fmaf(p2, a2.y, fmaf(p1, a1.y, fmaf(p0, a0.y, EPSV))));
                wd[2] = fmaf(p3, a3.z, fmaf(p2, a2.z, fmaf(p1, a1.z, fmaf(p0, a0.z, EPSV))));
                wd[3] = fmaf(p3, a3.w, fmaf(p2, a2.w, fmaf(p1, a1.w, fmaf(p0, a0.w, EPSV))));
            }
        }
        CP_WAIT0();
        __syncthreads();

        /* ---- QK^T: S = Qh*Kh (single-term) ---- */
        float S[2][4][4];
#pragma unroll
        for (int it = 0; it < 2; it++)
#pragma unroll
            for (int j8 = 0; j8 < 4; j8++)
#pragma unroll
                for (int c = 0; c < 4; c++) S[it][j8][c] = 0.f;
#pragma unroll
        for (int j8 = 0; j8 < 4; j8++)
#pragma unroll
            for (int ks = 0; ks < 2; ks++) {
                int krow = j8 * 8 + (lane & 7);
                int kcol = 32 * h + ks * 16 + ((lane >> 3) & 1) * 8;
                uint32_t bh[2];
                ldsm2(bh, sb + OFF_K + krow * RSTRB + kcol * 2);
#pragma unroll
                for (int it = 0; it < 2; it++)
                    mma16816(S[it][j8], qh[it][ks], bh);
            }

        /* ---- p = w * exp(s*scale); single fp16 P (scaled) ---- */
        uint32_t ph[2][2][4];
#pragma unroll
        for (int it = 0; it < 2; it++)
#pragma unroll
            for (int j8 = 0; j8 < 4; j8++) {
                int r0 = it * 16 + (lane >> 2);
                int c0 = j8 * 8 + 2 * (lane & 3);
                const float* wr0 = Ws + (h * 32 + r0) * 33 + c0;
                const float* wr1 = Ws + (h * 32 + r0 + 8) * 33 + c0;
                float p0 = wr0[0] * __expf(S[it][j8][0] * QKSCALE);
                float p1 = wr0[1] * __expf(S[it][j8][1] * QKSCALE);
                float p2 = wr1[0] * __expf(S[it][j8][2] * QKSCALE);
                float p3 = wr1[1] * __expf(S[it][j8][3] * QKSCALE);
                rsum[it * 2 + 0] += p0 + p1;
                rsum[it * 2 + 1] += p2 + p3;
                __half f0 = __float2half_rn(p0 * PSCALE);
                __half f1 = __float2half_rn(p1 * PSCALE);
                __half f2 = __float2half_rn(p2 * PSCALE);
                __half f3 = __float2half_rn(p3 * PSCALE);
                int kc = j8 >> 1, sl = (j8 & 1) * 2;
                ph[it][kc][sl + 0] = packh(f0, f1);
                ph[it][kc][sl + 1] = packh(f2, f3);
            }

        /* ---- O += P @ Vh ---- */
#pragma unroll
        for (int n8 = 0; n8 < 4; n8++)
#pragma unroll
            for (int kc = 0; kc < 2; kc++) {
                int vrow = kc * 16 + (lane & 15);
                int vcol = 32 * h + n8 * 8;
                uint32_t vh[2];
                ldsm2t(vh, sb + OFF_V + vrow * RSTRB + vcol * 2);
#pragma unroll
                for (int it = 0; it < 2; it++)
                    mma16816(O[it][n8], ph[it][kc], vh);
            }
    }

    /* ---- epilogue ---- */
#pragma unroll
    for (int v = 0; v < 4; v++) {
        float x = rsum[v];
        x += __shfl_xor_sync(0xffffffffu, x, 1);
        x += __shfl_xor_sync(0xffffffffu, x, 2);
        rsum[v] = x;
    }
    if ((lane & 3) == 0) {
#pragma unroll
        for (int it = 0; it < 2; it++)
#pragma unroll
            for (int half = 0; half < 2; half++) {
                int row = it * 16 + (lane >> 2) + half * 8;
                g_pd[(size_t)sy * NTOK * NHEAD + (size_t)(i0 + row) * NHEAD + h] = rsum[it * 2 + half];
            }
    }
    float* pn = g_pn + (size_t)sy * NTOK * 256;
#pragma unroll
    for (int it = 0; it < 2; it++)
#pragma unroll
        for (int n8 = 0; n8 < 4; n8++) {
            int r0 = i0 + it * 16 + (lane >> 2);
            int c = 32 * h + n8 * 8 + 2 * (lane & 3);
            *(float2*)(pn + (size_t)r0 * 256 + c) =
                make_float2(O[it][n8][0] * INV_PSCALE, O[it][n8][1] * INV_PSCALE);
            *(float2*)(pn + (size_t)(r0 + 8) * 256 + c) =
                make_float2(O[it][n8][2] * INV_PSCALE, O[it][n8][3] * INV_PSCALE);
        }
}

/* ================================================================= */
extern "C" void kernel_launch(void* const* d_in, const int* in_sizes, int n_in,
                              void* d_out, int out_size)
{
    const float* x    = (const float*)d_in[0];
    const float* pi   = (const float*)d_in[1];
    const float* tau  = (const float*)d_in[2];
    const float* adjs = (const float*)d_in[3];
    const float* Wq   = (const float*)d_in[4];
    const float* Wk   = (const float*)d_in[5];
    const float* Wv   = (const float*)d_in[6];
    const float* Wo   = (const float*)d_in[7];
    float* out = (float*)d_out;

    cudaFuncSetAttribute(attn_mma, cudaFuncAttributeMaxDynamicSharedMemorySize, SMEM_BYTES);
    cudaFuncSetAttribute(hgemm_qkv, cudaFuncAttributeMaxDynamicSharedMemorySize, HSMEM);
    cudaFuncSetAttribute(hgemm_out, cudaFuncAttributeMaxDynamicSharedMemorySize, HSMEM);

    conv_inputs<<<768, 256>>>(x, Wq, Wk, Wv, Wo);
    hgemm_qkv<<<dim3(12, 32), 256, HSMEM>>>();
    attn_mma<<<dim3(NTOK / TIA, NSPL), 256, SMEM_BYTES>>>(pi, tau, adjs);
    combine_o<<<512, 256>>>();
    hgemm_out<<<dim3(4, 32), 256, HSMEM>>>(out);
}

// round 13
// speedup vs baseline: 2.0798x; 1.0540x over previous
#include <cuda_runtime.h>
#include <cuda_fp16.h>
#include <cstdint>

#define NTOK 2048
#define NHEAD 8
#define EPSV 1e-6f
#define QKSCALE 0.17677669529663687f
#define PSCALE 1024.0f
#define INV_PSCALE (1.0f / 1024.0f)
#define NSPL 4
#define JR (NTOK / NSPL)      /* 512 per split */
#define TIA 32
#define TJA 32
#define NJT (JR / TJA)        /* 16 tiles */
#define RSTRB 528             /* smem row stride bytes (264 fp16) */
#define PLANEB 16896          /* 32*528 */
#define NX (NTOK * 256)       /* 524288 */

typedef unsigned long long ull;

__device__ float g_pn[NSPL * NTOK * 256];
__device__ float g_pd[NSPL * NTOK * NHEAD];
__device__ __align__(16) __half g_Qhl[2 * NX];
__device__ __align__(16) __half g_Khl[2 * NX];
__device__ __align__(16) __half g_Vhl[2 * NX];
__device__ __align__(16) __half g_Xhl[2 * NX];    /* x planes; reused as O planes */
__device__ __align__(16) __half g_Wall[4 * 2 * 256 * 256];

/* ---------------- warp-mma / async helpers ---------------- */
__device__ __forceinline__ uint32_t smem_u32(const void* p) {
    uint32_t a;
    asm("{ .reg .u64 t; cvta.to.shared.u64 t, %1; cvt.u32.u64 %0, t; }" : "=r"(a) : "l"(p));
    return a;
}
__device__ __forceinline__ void mma16816(float* d, const uint32_t* a, const uint32_t* b) {
    asm("mma.sync.aligned.m16n8k16.row.col.f32.f16.f16.f32 "
        "{%0,%1,%2,%3}, {%4,%5,%6,%7}, {%8,%9}, {%0,%1,%2,%3};"
        : "+f"(d[0]), "+f"(d[1]), "+f"(d[2]), "+f"(d[3])
        : "r"(a[0]), "r"(a[1]), "r"(a[2]), "r"(a[3]), "r"(b[0]), "r"(b[1]));
}
__device__ __forceinline__ void ldsm4(uint32_t* r, uint32_t a) {
    asm volatile("ldmatrix.sync.aligned.m8n8.x4.shared.b16 {%0,%1,%2,%3}, [%4];"
                 : "=r"(r[0]), "=r"(r[1]), "=r"(r[2]), "=r"(r[3]) : "r"(a));
}
__device__ __forceinline__ void ldsm2(uint32_t* r, uint32_t a) {
    asm volatile("ldmatrix.sync.aligned.m8n8.x2.shared.b16 {%0,%1}, [%2];"
                 : "=r"(r[0]), "=r"(r[1]) : "r"(a));
}
__device__ __forceinline__ void ldsm2t(uint32_t* r, uint32_t a) {
    asm volatile("ldmatrix.sync.aligned.m8n8.x2.trans.shared.b16 {%0,%1}, [%2];"
                 : "=r"(r[0]), "=r"(r[1]) : "r"(a));
}
__device__ __forceinline__ void cpa16(uint32_t d, const void* s) {
    asm volatile("cp.async.ca.shared.global [%0], [%1], 16;" :: "r"(d), "l"(s));
}
#define CP_COMMIT() asm volatile("cp.async.commit_group;" ::: "memory")
#define CP_WAIT0()  asm volatile("cp.async.wait_group 0;" ::: "memory")
__device__ __forceinline__ void hiloh(float v, __half& h, __half& l) {
    h = __float2half_rn(v);
    l = __float2half_rn(v - __half2float(h));
}
__device__ __forceinline__ uint32_t packh(__half a, __half b) {
    return (uint32_t)*(unsigned short*)&a | ((uint32_t)*(unsigned short*)&b << 16);
}

/* =============== conv: x, Wq/Wk/Wv/Wo -> fp16 hi/lo planes =============== */
__global__ __launch_bounds__(256) void conv_inputs(const float* __restrict__ x,
                                                   const float* __restrict__ Wq,
                                                   const float* __restrict__ Wk,
                                                   const float* __restrict__ Wv,
                                                   const float* __restrict__ Wo)
{
    const int base = (blockIdx.x * 256 + threadIdx.x) * 4;
    float4 v;
    __half* dst;
    int stride;
    bool store_lo = true;
    if (base < NX) {
        v = *(const float4*)(x + base);
        dst = g_Xhl + base;
        stride = NX;
    } else {
        int wrem = base - NX;
        int wi = wrem >> 16, rem = wrem & 65535;
        const float* W = (wi == 0) ? Wq : (wi == 1) ? Wk : (wi == 2) ? Wv : Wo;
        v = *(const float4*)(W + rem);
        dst = g_Wall + wi * 131072 + rem;
        stride = 65536;
        store_lo = (wi == 3);   /* only Wo's lo plane is consumed (3-term out GEMM) */
    }
    __half h0, l0, h1, l1, h2, l2, h3, l3;
    hiloh(v.x, h0, l0); hiloh(v.y, h1, l1); hiloh(v.z, h2, l2); hiloh(v.w, h3, l3);
    *(ull*)dst = (ull)packh(h0, h1) | ((ull)packh(h2, h3) << 32);
    if (store_lo)
        *(ull*)(dst + stride) = (ull)packh(l0, l1) | ((ull)packh(l2, l3) << 32);
}

/* =============== hgemm body: planes/out = (A_planes @ W^T) =============== */
/* TO_PLANES: epilogue emits fp16 hi(-only) planes.  THREE_TERM: add ah*bl. */
#define HPLANE 33792          /* 64*528 */
#define HSMEM  135168

template<bool TO_PLANES, bool THREE_TERM>
__device__ __forceinline__ void hgemm_body(const __half* __restrict__ Asrc,
                                           const __half* __restrict__ wsrc,
                                           __half* __restrict__ Pdst,
                                           float* __restrict__ Fdst,
                                           int i0, int nw)
{
    extern __shared__ __align__(16) char hsm[];
    const uint32_t sA = smem_u32(hsm);
    const uint32_t sB = sA + 2 * HPLANE;

    const int t = threadIdx.x, lane = t & 31, w = t >> 5;

    for (int c = t; c < 2048; c += 256) {
        int row = c >> 5, ch = c & 31;
        cpa16(sA + row * RSTRB + ch * 16,          Asrc + (size_t)(i0 + row) * 256 + ch * 8);
        cpa16(sA + HPLANE + row * RSTRB + ch * 16, Asrc + NX + (size_t)(i0 + row) * 256 + ch * 8);
        cpa16(sB + row * RSTRB + ch * 16,          wsrc + (size_t)row * 256 + ch * 8);
        if (THREE_TERM)
            cpa16(sB + HPLANE + row * RSTRB + ch * 16, wsrc + 65536 + (size_t)row * 256 + ch * 8);
    }
    CP_COMMIT(); CP_WAIT0();
    __syncthreads();

    const int mrow = (w >> 1) * 16;
    const int ncol = (w & 1) * 32;

    float acc[4][4];
#pragma unroll
    for (int n8 = 0; n8 < 4; n8++)
#pragma unroll
        for (int c = 0; c < 4; c++) acc[n8][c] = 0.f;

#pragma unroll 4
    for (int ks = 0; ks < 16; ks++) {
        uint32_t ah[4], al[4];
        {
            int row = mrow + (lane & 15);
            int col = ks * 16 + (lane >> 4) * 8;
            uint32_t ad = sA + row * RSTRB + col * 2;
            ldsm4(ah, ad);
            ldsm4(al, ad + HPLANE);
        }
#pragma unroll
        for (int n8 = 0; n8 < 4; n8++) {
            int row = ncol + n8 * 8 + (lane & 7);
            int col = ks * 16 + ((lane >> 3) & 1) * 8;
            uint32_t bd = sB + row * RSTRB + col * 2;
            uint32_t bh[2];
            ldsm2(bh, bd);
            mma16816(acc[n8], ah, bh);
            mma16816(acc[n8], al, bh);
            if (THREE_TERM) {
                uint32_t bl[2];
                ldsm2(bl, bd + HPLANE);
                mma16816(acc[n8], ah, bl);
            }
        }
    }

#pragma unroll
    for (int n8 = 0; n8 < 4; n8++) {
        int cg = nw + ncol + n8 * 8 + 2 * (lane & 3);
        int rg = i0 + mrow + (lane >> 2);
        if (TO_PLANES) {
            /* hi planes only — lo planes of Q/K/V are dead downstream */
            *(uint32_t*)(Pdst + (size_t)rg * 256 + cg) =
                packh(__float2half_rn(acc[n8][0]), __float2half_rn(acc[n8][1]));
            *(uint32_t*)(Pdst + (size_t)(rg + 8) * 256 + cg) =
                packh(__float2half_rn(acc[n8][2]), __float2half_rn(acc[n8][3]));
        } else {
            *(float2*)(Fdst + (size_t)rg * 256 + cg) = make_float2(acc[n8][0], acc[n8][1]);
            *(float2*)(Fdst + (size_t)(rg + 8) * 256 + cg) = make_float2(acc[n8][2], acc[n8][3]);
        }
    }
}

__global__ __launch_bounds__(256) void hgemm_qkv()
{
    const int bn = blockIdx.x;            /* 0..11 */
    const int widx = bn >> 2;
    const int nw = (bn & 3) * 64;
    __half* P = (widx == 0) ? g_Qhl : (widx == 1) ? g_Khl : g_Vhl;
    hgemm_body<true, false>(g_Xhl, g_Wall + widx * 131072 + nw * 256, P, nullptr,
                            blockIdx.y * 64, nw);
}

__global__ __launch_bounds__(256) void hgemm_out(float* __restrict__ out)
{
    const int nw = blockIdx.x * 64;
    hgemm_body<false, true>(g_Xhl, g_Wall + 3 * 131072 + nw * 256, nullptr, out,
                            blockIdx.y * 64, nw);
}

/* =============== combine_o: fold split partials -> O fp16 planes (reuse g_Xhl) =============== */
__global__ __launch_bounds__(256) void combine_o()
{
    const int idx4 = blockIdx.x * 256 + threadIdx.x;   /* 0..131071 */
    const int row = idx4 >> 6;
    const int c0 = (idx4 & 63) * 4;
    float4 n = *(const float4*)(g_pn + (size_t)row * 256 + c0);
    float den = g_pd[row * NHEAD + (c0 >> 5)];
#pragma unroll
    for (int s = 1; s < NSPL; s++) {
        float4 n2 = *(const float4*)(g_pn + (size_t)s * NTOK * 256 + (size_t)row * 256 + c0);
        n.x += n2.x; n.y += n2.y; n.z += n2.z; n.w += n2.w;
        den += g_pd[s * NTOK * NHEAD + row * NHEAD + (c0 >> 5)];
    }
    float inv = 1.0f / den;
    __half h0, l0, h1, l1, h2, l2, h3, l3;
    hiloh(n.x * inv, h0, l0); hiloh(n.y * inv, h1, l1);
    hiloh(n.z * inv, h2, l2); hiloh(n.w * inv, h3, l3);
    __half* d = g_Xhl + (size_t)row * 256 + c0;
    *(ull*)d        = (ull)packh(h0, h1) | ((ull)packh(h2, h3) << 32);
    *(ull*)(d + NX) = (ull)packh(l0, l1) | ((ull)packh(l2, l3) << 32);
}

/* =============== warp-mma attention: Qh-only QK, Kh/Vh tiles, 2 CTAs/SM =============== */
#define OFF_K   0                       /* 1 plane: 16896 */
#define OFF_V   PLANEB                  /* 1 plane: 16896 */
#define OFF_W   (2 * PLANEB)            /* float Ws[8][32][33] = 33792 */
#define OFF_PIT (OFF_W + 33792)         /* 4096 */
#define SMEM_BYTES (OFF_PIT + 4096)     /* 71680 */

__global__ __launch_bounds__(256, 2) void attn_mma(
    const float* __restrict__ pi, const float* __restrict__ tau,
    const float* __restrict__ adjs)
{
    extern __shared__ __align__(16) char smraw[];
    const uint32_t sb = smem_u32(smraw);
    float* Ws   = (float*)(smraw + OFF_W);
    float* pits = (float*)(smraw + OFF_PIT);

    const int t = threadIdx.x, lane = t & 31, h = t >> 5;
    const int i0 = blockIdx.x * TIA;
    const int sy = blockIdx.y;
    const int jbase = sy * JR;
    const size_t NN = (size_t)NTOK * NTOK;

    for (int idx = t; idx < TIA * 32; idx += 256) {
        int hm = idx & 31;
        pits[idx] = tau[hm >> 2] * pi[(size_t)(i0 + (idx >> 5)) * 32 + hm];
    }

    /* ---- stage Q hi plane into K buffer, pull A-fragments ---- */
#pragma unroll
    for (int k = 0; k < 4; k++) {
        int idx = t + k * 256;              /* 1024 chunks of 16B */
        int row = idx >> 5, c16 = idx & 31;
        const __half* s = g_Qhl + (size_t)(i0 + row) * 256 + c16 * 8;
        ull v = *(const ull*)s, v2 = *(const ull*)(s + 4);
        char* d = smraw + OFF_K + row * RSTRB + c16 * 16;
        *(ull*)d = v; *(ull*)(d + 8) = v2;
    }
    __syncthreads();
    uint32_t qh[2][2][4];
#pragma unroll
    for (int it = 0; it < 2; it++)
#pragma unroll
        for (int ks = 0; ks < 2; ks++) {
            int row = it * 16 + (lane & 15);
            int col = 32 * h + ks * 16 + (lane >> 4) * 8;
            ldsm4(qh[it][ks], sb + OFF_K + row * RSTRB + col * 2);
        }

    /* per-thread cp.async mapping: 8 chunks (Kh, Vh planes) */
    uint32_t cdst[8];
    const __half* csrc_base[8];
    int crow[8];
#pragma unroll
    for (int k = 0; k < 8; k++) {
        int idx = t + k * 256;              /* 2048: plane(K/V) x row x c16 */
        int plane = idx >> 10, r3 = idx & 1023, row = r3 >> 5, c16 = r3 & 31;
        cdst[k] = sb + (plane ? OFF_V : OFF_K) + row * RSTRB + c16 * 16;
        csrc_base[k] = (plane ? g_Vhl : g_Khl) + c16 * 8;
        crow[k] = row;
    }

    float O[2][4][4];
#pragma unroll
    for (int it = 0; it < 2; it++)
#pragma unroll
        for (int n8 = 0; n8 < 4; n8++)
#pragma unroll
            for (int c = 0; c < 4; c++) O[it][n8][c] = 0.f;
    float rsum[4] = {0.f, 0.f, 0.f, 0.f};

    const int wi = t >> 3;
    const int wj4 = (t & 7) * 4;

    for (int jt = 0; jt < NJT; jt++) {
        const int j0 = jbase + jt * TJA;
        __syncthreads();   /* reads of previous tile (and Q fragments) done */

        /* issue this tile's K/V loads */
#pragma unroll
        for (int k = 0; k < 8; k++)
            cpa16(cdst[k], csrc_base[k] + (size_t)(j0 + crow[k]) * 256);
        CP_COMMIT();

        /* adjs loads + graph weights (overlap the cp.async) */
        const float* ab = adjs + (size_t)(i0 + wi) * NTOK + j0 + wj4;
        float4 a0 = *(const float4*)(ab);
        float4 a1 = *(const float4*)(ab + NN);
        float4 a2 = *(const float4*)(ab + 2 * NN);
        float4 a3 = *(const float4*)(ab + 3 * NN);
        {
            const float* pp = pits + wi * 32;
#pragma unroll
            for (int hh = 0; hh < NHEAD; hh++) {
                float p0 = pp[hh * 4 + 0], p1 = pp[hh * 4 + 1], p2 = pp[hh * 4 + 2], p3 = pp[hh * 4 + 3];
                float* wd = Ws + (hh * 32 + wi) * 33 + wj4;
                wd[0] = fmaf(p3, a3.x, fmaf(p2, a2.x, fmaf(p1, a1.x, fmaf(p0, a0.x, EPSV))));
                wd[1] = fmaf(p3, a3.y, fmaf(p2, a2.y, fmaf(p1, a1.y, fmaf(p0, a0.y, EPSV))));
                wd[2] = fmaf(p3, a3.z, fmaf(p2, a2.z, fmaf(p1, a1.z, fmaf(p0, a0.z, EPSV))));
                wd[3] = fmaf(p3, a3.w, fmaf(p2, a2.w, fmaf(p1, a1.w, fmaf(p0, a0.w, EPSV))));
            }
        }
        CP_WAIT0();
        __syncthreads();

        /* ---- QK^T: S = Qh*Kh ---- */
        float S[2][4][4];
#pragma unroll
        for (int it = 0; it < 2; it++)
#pragma unroll
            for (int j8 = 0; j8 < 4; j8++)
#pragma unroll
                for (int c = 0; c < 4; c++) S[it][j8][c] = 0.f;
#pragma unroll
        for (int j8 = 0; j8 < 4; j8++)
#pragma unroll
            for (int ks = 0; ks < 2; ks++) {
                int krow = j8 * 8 + (lane & 7);
                int kcol = 32 * h + ks * 16 + ((lane >> 3) & 1) * 8;
                uint32_t bh[2];
                ldsm2(bh, sb + OFF_K + krow * RSTRB + kcol * 2);
#pragma unroll
                for (int it = 0; it < 2; it++)
                    mma16816(S[it][j8], qh[it][ks], bh);
            }

        /* ---- p = w * exp(s*scale); single fp16 P (scaled) ---- */
        uint32_t ph[2][2][4];
#pragma unroll
        for (int it = 0; it < 2; it++)
#pragma unroll
            for (int j8 = 0; j8 < 4; j8++) {
                int r0 = it * 16 + (lane >> 2);
                int c0 = j8 * 8 + 2 * (lane & 3);
                const float* wr0 = Ws + (h * 32 + r0) * 33 + c0;
                const float* wr1 = Ws + (h * 32 + r0 + 8) * 33 + c0;
                float p0 = wr0[0] * __expf(S[it][j8][0] * QKSCALE);
                float p1 = wr0[1] * __expf(S[it][j8][1] * QKSCALE);
                float p2 = wr1[0] * __expf(S[it][j8][2] * QKSCALE);
                float p3 = wr1[1] * __expf(S[it][j8][3] * QKSCALE);
                rsum[it * 2 + 0] += p0 + p1;
                rsum[it * 2 + 1] += p2 + p3;
                __half f0 = __float2half_rn(p0 * PSCALE);
                __half f1 = __float2half_rn(p1 * PSCALE);
                __half f2 = __float2half_rn(p2 * PSCALE);
                __half f3 = __float2half_rn(p3 * PSCALE);
                int kc = j8 >> 1, sl = (j8 & 1) * 2;
                ph[it][kc][sl + 0] = packh(f0, f1);
                ph[it][kc][sl + 1] = packh(f2, f3);
            }

        /* ---- O += P @ Vh ---- */
#pragma unroll
        for (int n8 = 0; n8 < 4; n8++)
#pragma unroll
            for (int kc = 0; kc < 2; kc++) {
                int vrow = kc * 16 + (lane & 15);
                int vcol = 32 * h + n8 * 8;
                uint32_t vh[2];
                ldsm2t(vh, sb + OFF_V + vrow * RSTRB + vcol * 2);
#pragma unroll
                for (int it = 0; it < 2; it++)
                    mma16816(O[it][n8], ph[it][kc], vh);
            }
    }

    /* ---- epilogue ---- */
#pragma unroll
    for (int v = 0; v < 4; v++) {
        float x = rsum[v];
        x += __shfl_xor_sync(0xffffffffu, x, 1);
        x += __shfl_xor_sync(0xffffffffu, x, 2);
        rsum[v] = x;
    }
    if ((lane & 3) == 0) {
#pragma unroll
        for (int it = 0; it < 2; it++)
#pragma unroll
            for (int half = 0; half < 2; half++) {
                int row = it * 16 + (lane >> 2) + half * 8;
                g_pd[(size_t)sy * NTOK * NHEAD + (size_t)(i0 + row) * NHEAD + h] = rsum[it * 2 + half];
            }
    }
    float* pn = g_pn + (size_t)sy * NTOK * 256;
#pragma unroll
    for (int it = 0; it < 2; it++)
#pragma unroll
        for (int n8 = 0; n8 < 4; n8++) {
            int r0 = i0 + it * 16 + (lane >> 2);
            int c = 32 * h + n8 * 8 + 2 * (lane & 3);
            *(float2*)(pn + (size_t)r0 * 256 + c) =
                make_float2(O[it][n8][0] * INV_PSCALE, O[it][n8][1] * INV_PSCALE);
            *(float2*)(pn + (size_t)(r0 + 8) * 256 + c) =
                make_float2(O[it][n8][2] * INV_PSCALE, O[it][n8][3] * INV_PSCALE);
        }
}

/* ================================================================= */
extern "C" void kernel_launch(void* const* d_in, const int* in_sizes, int n_in,
                              void* d_out, int out_size)
{
    const float* x    = (const float*)d_in[0];
    const float* pi   = (const float*)d_in[1];
    const float* tau  = (const float*)d_in[2];
    const float* adjs = (const float*)d_in[3];
    const float* Wq   = (const float*)d_in[4];
    const float* Wk   = (const float*)d_in[5];
    const float* Wv   = (const float*)d_in[6];
    const float* Wo   = (const float*)d_in[7];
    float* out = (float*)d_out;

    cudaFuncSetAttribute(attn_mma, cudaFuncAttributeMaxDynamicSharedMemorySize, SMEM_BYTES);
    cudaFuncSetAttribute(hgemm_qkv, cudaFuncAttributeMaxDynamicSharedMemorySize, HSMEM);
    cudaFuncSetAttribute(hgemm_out, cudaFuncAttributeMaxDynamicSharedMemorySize, HSMEM);

    conv_inputs<<<768, 256>>>(x, Wq, Wk, Wv, Wo);
    hgemm_qkv<<<dim3(12, 32), 256, HSMEM>>>();
    attn_mma<<<dim3(NTOK / TIA, NSPL), 256, SMEM_BYTES>>>(pi, tau, adjs);
    combine_o<<<512, 256>>>();
    hgemm_out<<<dim3(4, 32), 256, HSMEM>>>(out);
}